// round 1
// baseline (speedup 1.0000x reference)
#include <cuda_runtime.h>
#include <math.h>

#define BATCH 8
#define CIN   256
#define CI    128
#define NSP   6272   // 8*28*28
#define MSP   1568   // 8*14*14

// ---- scratch (static device arrays; allocation-free) ----
__device__ float g_Tq  [BATCH * NSP * CI];   // theta(x), full res  (n, ci)
__device__ float g_Tphi[BATCH * NSP * CI];   // phi(x),   full res
__device__ float g_Tg  [BATCH * NSP * CI];   // g(x),     full res
__device__ float g_Kp  [BATCH * MSP * CI];   // pooled phi (m, ci)
__device__ float g_Vp  [BATCH * MSP * CI];   // pooled g   (m, ci)
__device__ float g_Y   [BATCH * NSP * CI];   // attention output (n, ci)

typedef unsigned long long ull;

__device__ __forceinline__ void fma2(ull &d, ull a, ull b) {
    asm("fma.rn.f32x2 %0, %1, %2, %0;" : "+l"(d) : "l"(a), "l"(b));
}
__device__ __forceinline__ ull mul2(ull a, ull b) {
    ull d; asm("mul.rn.f32x2 %0, %1, %2;" : "=l"(d) : "l"(a), "l"(b)); return d;
}
__device__ __forceinline__ float hsum2(ull v) {
    float a, b; asm("mov.b64 {%0,%1}, %2;" : "=f"(a), "=f"(b) : "l"(v)); return a + b;
}
__device__ __forceinline__ ull pack2(float a, float b) {
    ull d; asm("mov.b64 %0, {%1,%2};" : "=l"(d) : "f"(a), "f"(b)); return d;
}

// ============================================================
// Kernel 1: projections.  out[n, j] = sum_c x[b,c,n] * W[j,c] + bias[j]
// grid (98, 6, 8): x = n-tile(64), y = j-tile (0,1:theta 2,3:phi 4,5:g), z = batch
// packed over c-parity (fma.rn.f32x2)
// ============================================================
__global__ __launch_bounds__(256) void proj_kernel(
    const float* __restrict__ x,
    const float* __restrict__ th_w, const float* __restrict__ th_b,
    const float* __restrict__ ph_w, const float* __restrict__ ph_b,
    const float* __restrict__ gw,   const float* __restrict__ gb)
{
    __shared__ __align__(16) float Xs[8 * 132];  // [cpair][n*2 + parity]
    __shared__ __align__(16) float Ws[8 * 132];  // [cpair][j*2 + parity]

    const int tid = threadIdx.x;
    const int tx = tid & 15, ty = tid >> 4;
    const int nb = blockIdx.x * 64;
    const int jt = blockIdx.y;
    const int b  = blockIdx.z;

    const float *wp, *bp; float *outp;
    const int wsel = jt >> 1;
    if      (wsel == 0) { wp = th_w; bp = th_b; outp = g_Tq;   }
    else if (wsel == 1) { wp = ph_w; bp = ph_b; outp = g_Tphi; }
    else                { wp = gw;   bp = gb;   outp = g_Tg;   }
    const int j0 = (jt & 1) * 64;

    ull acc[4][4];
#pragma unroll
    for (int i = 0; i < 4; i++)
#pragma unroll
        for (int j = 0; j < 4; j++) acc[i][j] = 0ULL;

    const float* xb = x + (size_t)b * CIN * NSP;

    for (int kt = 0; kt < CIN / 16; kt++) {
        const int c0 = kt * 16;
        __syncthreads();
        // X tile: 16 c-rows x 64 n (coalesced along n)
        {
            int idx = tid;
#pragma unroll
            for (int r = 0; r < 4; r++) {
                int cc = idx >> 6, nn = idx & 63;
                Xs[(cc >> 1) * 132 + nn * 2 + (cc & 1)] =
                    xb[(size_t)(c0 + cc) * NSP + nb + nn];
                idx += 256;
            }
        }
        // W tile: 64 j-rows x 16 c
        {
            int idx = tid;
#pragma unroll
            for (int r = 0; r < 4; r++) {
                int jj = idx >> 4, cc = idx & 15;
                Ws[(cc >> 1) * 132 + jj * 2 + (cc & 1)] =
                    wp[(size_t)(j0 + jj) * CIN + c0 + cc];
                idx += 256;
            }
        }
        __syncthreads();
#pragma unroll
        for (int cp = 0; cp < 8; cp++) {
            ull a2[4], b2[4];
#pragma unroll
            for (int i = 0; i < 4; i++)
                a2[i] = *(const ull*)&Xs[cp * 132 + (ty * 4 + i) * 2];
#pragma unroll
            for (int j = 0; j < 4; j++)
                b2[j] = *(const ull*)&Ws[cp * 132 + (tx + 16 * j) * 2];
#pragma unroll
            for (int i = 0; i < 4; i++)
#pragma unroll
                for (int j = 0; j < 4; j++) fma2(acc[i][j], a2[i], b2[j]);
        }
    }
#pragma unroll
    for (int i = 0; i < 4; i++) {
        const int n = nb + ty * 4 + i;
        float* orow = outp + ((size_t)b * NSP + n) * CI;
#pragma unroll
        for (int j = 0; j < 4; j++) {
            const int c = tx + 16 * j;
            orow[j0 + c] = hsum2(acc[i][j]) + bp[j0 + c];
        }
    }
}

// ============================================================
// Kernel 2: 2x2 spatial maxpool of phi/g.  grid = B*MSP blocks, 128 threads
// ============================================================
__global__ void pool_kernel()
{
    const int bm = blockIdx.x;
    const int b = bm / MSP, m = bm % MSP;
    const int t = m / 196, rem = m % 196;
    const int h2 = rem / 14, w2 = rem % 14;
    const int n0 = t * 784 + (2 * h2) * 28 + 2 * w2;
    const int ci = threadIdx.x;
    const size_t base = (size_t)b * NSP * CI;

    const float* p = g_Tphi;
    float pv = fmaxf(fmaxf(p[base + (size_t)n0 * CI + ci],
                           p[base + (size_t)(n0 + 1) * CI + ci]),
                     fmaxf(p[base + (size_t)(n0 + 28) * CI + ci],
                           p[base + (size_t)(n0 + 29) * CI + ci]));
    g_Kp[((size_t)b * MSP + m) * CI + ci] = pv;

    const float* gg = g_Tg;
    float gv = fmaxf(fmaxf(gg[base + (size_t)n0 * CI + ci],
                           gg[base + (size_t)(n0 + 1) * CI + ci]),
                     fmaxf(gg[base + (size_t)(n0 + 28) * CI + ci],
                           gg[base + (size_t)(n0 + 29) * CI + ci]));
    g_Vp[((size_t)b * MSP + m) * CI + ci] = gv;
}

// ============================================================
// Kernel 3: flash attention, fp32, f32x2 inner loops.
// grid (98, 8): x = q-tile(64 rows), y = batch.  256 threads (16x16, 4x4 / 4x8 micro)
// smem: Qs/Ks float2[64dp][65] (transposed pairs), Vt float[128c][66m], Ps float[64r][66m]
// ============================================================
#define ATTN_SMEM (64*65*8*2 + 128*66*4 + 64*66*4)   // 117248 bytes

__global__ __launch_bounds__(256) void attn_kernel()
{
    extern __shared__ __align__(16) float sm[];
    float2* Qs = (float2*)sm;            // 64*65
    float2* Ks = Qs + 64 * 65;           // 64*65
    float*  Vt = (float*)(Ks + 64 * 65); // 128*66
    float*  Ps = Vt + 128 * 66;          // 64*66

    const int tid = threadIdx.x;
    const int tx = tid & 15, ty = tid >> 4;
    const int qb = blockIdx.x * 64;
    const int b  = blockIdx.y;

    const float* Q = g_Tq + ((size_t)b * NSP + qb) * CI;
    const float* K = g_Kp + (size_t)b * MSP * CI;
    const float* V = g_Vp + (size_t)b * MSP * CI;

    // load Q tile transposed-by-pairs
    for (int idx = tid; idx < 64 * 64; idx += 256) {
        int dp = idx & 63, row = idx >> 6;
        Qs[dp * 65 + row] = *(const float2*)&Q[row * CI + dp * 2];
    }

    ull Oacc[4][8];
#pragma unroll
    for (int i = 0; i < 4; i++)
#pragma unroll
        for (int j = 0; j < 8; j++) Oacc[i][j] = 0ULL;
    float m_run[4] = {-1e30f, -1e30f, -1e30f, -1e30f};
    float l_run[4] = {0.f, 0.f, 0.f, 0.f};

    for (int kt = 0; kt < 25; kt++) {
        const int kvb = kt * 64;
        int kvn = MSP - kvb; if (kvn > 64) kvn = 64;

        __syncthreads();  // prior PV done (and Q visible on first iter)
        // K tile transposed-by-pairs (zero-fill tail)
        for (int idx = tid; idx < 64 * 64; idx += 256) {
            int dp = idx & 63, row = idx >> 6;
            float2 v = make_float2(0.f, 0.f);
            if (row < kvn) v = *(const float2*)&K[(size_t)(kvb + row) * CI + dp * 2];
            Ks[dp * 65 + row] = v;
        }
        // V tile fully transposed (c-major, m contiguous)
        for (int idx = tid; idx < 64 * 128; idx += 256) {
            int c = idx & 127, row = idx >> 7;
            float v = 0.f;
            if (row < kvn) v = V[(size_t)(kvb + row) * CI + c];
            Vt[c * 66 + row] = v;
        }
        __syncthreads();

        // S = Q K^T (packed over d-parity)
        ull S2[4][4];
#pragma unroll
        for (int i = 0; i < 4; i++)
#pragma unroll
            for (int j = 0; j < 4; j++) S2[i][j] = 0ULL;
#pragma unroll 8
        for (int dp = 0; dp < 64; dp++) {
            ull qq[4], kk[4];
#pragma unroll
            for (int i = 0; i < 4; i++)
                qq[i] = *(const ull*)&Qs[dp * 65 + ty * 4 + i];
#pragma unroll
            for (int j = 0; j < 4; j++)
                kk[j] = *(const ull*)&Ks[dp * 65 + tx + 16 * j];
#pragma unroll
            for (int i = 0; i < 4; i++)
#pragma unroll
                for (int j = 0; j < 4; j++) fma2(S2[i][j], qq[i], kk[j]);
        }
        float S[4][4];
#pragma unroll
        for (int i = 0; i < 4; i++)
#pragma unroll
            for (int j = 0; j < 4; j++) S[i][j] = hsum2(S2[i][j]);
        if (kvn < 64) {
#pragma unroll
            for (int j = 0; j < 4; j++)
                if (tx + 16 * j >= kvn) {
#pragma unroll
                    for (int i = 0; i < 4; i++) S[i][j] = -1e30f;
                }
        }

        // online softmax
#pragma unroll
        for (int i = 0; i < 4; i++) {
            float rm = fmaxf(fmaxf(S[i][0], S[i][1]), fmaxf(S[i][2], S[i][3]));
            rm = fmaxf(rm, __shfl_xor_sync(0xffffffffu, rm, 1));
            rm = fmaxf(rm, __shfl_xor_sync(0xffffffffu, rm, 2));
            rm = fmaxf(rm, __shfl_xor_sync(0xffffffffu, rm, 4));
            rm = fmaxf(rm, __shfl_xor_sync(0xffffffffu, rm, 8));
            const float mn = fmaxf(m_run[i], rm);
            const float f  = __expf(m_run[i] - mn);
            m_run[i] = mn;
            float s = 0.f;
#pragma unroll
            for (int j = 0; j < 4; j++) {
                float p = __expf(S[i][j] - mn);
                Ps[(ty * 4 + i) * 66 + tx + 16 * j] = p;
                s += p;
            }
            s += __shfl_xor_sync(0xffffffffu, s, 1);
            s += __shfl_xor_sync(0xffffffffu, s, 2);
            s += __shfl_xor_sync(0xffffffffu, s, 4);
            s += __shfl_xor_sync(0xffffffffu, s, 8);
            l_run[i] = l_run[i] * f + s;
            const ull ff = pack2(f, f);
#pragma unroll
            for (int j = 0; j < 8; j++) Oacc[i][j] = mul2(Oacc[i][j], ff);
        }
        __syncthreads();

        // O += P V (packed over m-parity)
#pragma unroll 4
        for (int mp = 0; mp < 32; mp++) {
            ull pp[4], vv[8];
#pragma unroll
            for (int i = 0; i < 4; i++)
                pp[i] = *(const ull*)&Ps[(ty * 4 + i) * 66 + mp * 2];
#pragma unroll
            for (int j = 0; j < 8; j++)
                vv[j] = *(const ull*)&Vt[(tx + 16 * j) * 66 + mp * 2];
#pragma unroll
            for (int i = 0; i < 4; i++)
#pragma unroll
                for (int j = 0; j < 8; j++) fma2(Oacc[i][j], pp[i], vv[j]);
        }
    }

    // y = O / l
#pragma unroll
    for (int i = 0; i < 4; i++) {
        const float inv = 1.0f / l_run[i];
        float* yr = g_Y + ((size_t)b * NSP + qb + ty * 4 + i) * CI;
#pragma unroll
        for (int j = 0; j < 8; j++)
            yr[tx + 16 * j] = hsum2(Oacc[i][j]) * inv;
    }
}

// ============================================================
// Kernel 4: out[b,co,n] = sum_ci y[b,n,ci] * W_w[co,ci] + W_b[co] + x[b,co,n]
// grid (98, 4, 8): n-tile(64), co-tile(64), batch.  rows=co (ty), cols=n (tx)
// ============================================================
__global__ __launch_bounds__(256) void out_kernel(
    const float* __restrict__ x,
    const float* __restrict__ Ww, const float* __restrict__ Wb,
    float* __restrict__ out)
{
    __shared__ __align__(16) float Ys[8 * 132];  // [cipair][n*2 + parity]
    __shared__ __align__(16) float Ws[8 * 132];  // [cipair][co*2 + parity]

    const int tid = threadIdx.x;
    const int tx = tid & 15, ty = tid >> 4;
    const int nb  = blockIdx.x * 64;
    const int co0 = blockIdx.y * 64;
    const int b   = blockIdx.z;

    ull acc[4][4];
#pragma unroll
    for (int i = 0; i < 4; i++)
#pragma unroll
        for (int j = 0; j < 4; j++) acc[i][j] = 0ULL;

    const float* yb = g_Y + (size_t)b * NSP * CI;

    for (int kt = 0; kt < CI / 16; kt++) {
        const int c0 = kt * 16;
        __syncthreads();
        {
            int idx = tid;
#pragma unroll
            for (int r = 0; r < 4; r++) {
                int nn = idx >> 4, cc = idx & 15;
                Ys[(cc >> 1) * 132 + nn * 2 + (cc & 1)] =
                    yb[(size_t)(nb + nn) * CI + c0 + cc];
                idx += 256;
            }
        }
        {
            int idx = tid;
#pragma unroll
            for (int r = 0; r < 4; r++) {
                int jj = idx >> 4, cc = idx & 15;
                Ws[(cc >> 1) * 132 + jj * 2 + (cc & 1)] =
                    Ww[(size_t)(co0 + jj) * CI + c0 + cc];
                idx += 256;
            }
        }
        __syncthreads();
#pragma unroll
        for (int cp = 0; cp < 8; cp++) {
            ull a2[4], b2[4];
#pragma unroll
            for (int i = 0; i < 4; i++)
                a2[i] = *(const ull*)&Ws[cp * 132 + (ty * 4 + i) * 2];
#pragma unroll
            for (int j = 0; j < 4; j++)
                b2[j] = *(const ull*)&Ys[cp * 132 + (tx + 16 * j) * 2];
#pragma unroll
            for (int i = 0; i < 4; i++)
#pragma unroll
                for (int j = 0; j < 4; j++) fma2(acc[i][j], a2[i], b2[j]);
        }
    }
#pragma unroll
    for (int i = 0; i < 4; i++) {
        const int co = co0 + ty * 4 + i;
        const float bias = Wb[co];
        const float* xr = x   + ((size_t)b * CIN + co) * NSP;
        float*      orow = out + ((size_t)b * CIN + co) * NSP;
#pragma unroll
        for (int j = 0; j < 4; j++) {
            const int n = nb + tx + 16 * j;
            orow[n] = hsum2(acc[i][j]) + bias + xr[n];
        }
    }
}

// ============================================================
extern "C" void kernel_launch(void* const* d_in, const int* in_sizes, int n_in,
                              void* d_out, int out_size)
{
    const float* x    = (const float*)d_in[0];
    const float* g_w  = (const float*)d_in[1];
    const float* g_b  = (const float*)d_in[2];
    const float* th_w = (const float*)d_in[3];
    const float* th_b = (const float*)d_in[4];
    const float* ph_w = (const float*)d_in[5];
    const float* ph_b = (const float*)d_in[6];
    const float* W_w  = (const float*)d_in[7];
    const float* W_b  = (const float*)d_in[8];
    float* out = (float*)d_out;

    cudaFuncSetAttribute(attn_kernel,
                         cudaFuncAttributeMaxDynamicSharedMemorySize, ATTN_SMEM);

    dim3 g1(NSP / 64, 6, BATCH);
    proj_kernel<<<g1, 256>>>(x, th_w, th_b, ph_w, ph_b, g_w, g_b);

    pool_kernel<<<BATCH * MSP, 128>>>();

    dim3 g2(NSP / 64, BATCH);
    attn_kernel<<<g2, 256, ATTN_SMEM>>>();

    dim3 g3(NSP / 64, CIN / 64, BATCH);
    out_kernel<<<g3, 256>>>(x, W_w, W_b, out);
}

// round 4
// speedup vs baseline: 2.5607x; 2.5607x over previous
#include <cuda_runtime.h>
#include <cuda_bf16.h>
#include <cstdint>
#include <math.h>

#define BATCH 8
#define CIN   256
#define CI    128
#define NSP   6272   // 8*28*28
#define MSP   1568   // 8*14*14

// ---- scratch (static device arrays; allocation-free) ----
__device__ float g_Tphi[BATCH * NSP * CI];
__device__ float g_Tg  [BATCH * NSP * CI];
__device__ float g_Y   [BATCH * NSP * CI];
__device__ __nv_bfloat16 g_Qh[BATCH * NSP * CI];
__device__ __nv_bfloat16 g_Ql[BATCH * NSP * CI];
__device__ __nv_bfloat16 g_Kh[BATCH * MSP * CI];
__device__ __nv_bfloat16 g_Kl[BATCH * MSP * CI];
__device__ __nv_bfloat16 g_Vh[BATCH * MSP * CI];   // (b, m, ci)
__device__ __nv_bfloat16 g_Vl[BATCH * MSP * CI];

typedef unsigned long long ull;

__device__ __forceinline__ void fma2(ull &d, ull a, ull b) {
    asm("fma.rn.f32x2 %0, %1, %2, %0;" : "+l"(d) : "l"(a), "l"(b));
}
__device__ __forceinline__ float hsum2(ull v) {
    float a, b; asm("mov.b64 {%0,%1}, %2;" : "=f"(a), "=f"(b) : "l"(v)); return a + b;
}
__device__ __forceinline__ uint32_t smem_u32(const void* p) {
    uint32_t a;
    asm("{ .reg .u64 t; cvta.to.shared.u64 t, %1; cvt.u32.u64 %0, t; }"
        : "=r"(a) : "l"(p));
    return a;
}

// ---- mma.sync helpers (sm_80 baseline ISA; compiles under compute_103) ----
__device__ __forceinline__ void ldsm4(uint32_t (&r)[4], uint32_t addr) {
    asm volatile("ldmatrix.sync.aligned.m8n8.x4.shared.b16 {%0,%1,%2,%3}, [%4];"
        : "=r"(r[0]), "=r"(r[1]), "=r"(r[2]), "=r"(r[3]) : "r"(addr));
}
__device__ __forceinline__ void ldsm4t(uint32_t (&r)[4], uint32_t addr) {
    asm volatile("ldmatrix.sync.aligned.m8n8.x4.trans.shared.b16 {%0,%1,%2,%3}, [%4];"
        : "=r"(r[0]), "=r"(r[1]), "=r"(r[2]), "=r"(r[3]) : "r"(addr));
}
__device__ __forceinline__ void mma16816(float (&d)[4], const uint32_t (&a)[4],
                                         uint32_t b0, uint32_t b1) {
    asm volatile("mma.sync.aligned.m16n8k16.row.col.f32.bf16.bf16.f32 "
        "{%0,%1,%2,%3}, {%4,%5,%6,%7}, {%8,%9}, {%0,%1,%2,%3};"
        : "+f"(d[0]), "+f"(d[1]), "+f"(d[2]), "+f"(d[3])
        : "r"(a[0]), "r"(a[1]), "r"(a[2]), "r"(a[3]), "r"(b0), "r"(b1));
}

// ============================================================
// Kernel 1: projections (f32x2 SGEMM).  theta -> bf16 hi/lo (Q), phi/g -> f32
// grid (98, 6, 8)
// ============================================================
__global__ __launch_bounds__(256) void proj_kernel(
    const float* __restrict__ x,
    const float* __restrict__ th_w, const float* __restrict__ th_b,
    const float* __restrict__ ph_w, const float* __restrict__ ph_b,
    const float* __restrict__ gw,   const float* __restrict__ gb)
{
    __shared__ __align__(16) float Xs[8 * 132];
    __shared__ __align__(16) float Ws[8 * 132];

    const int tid = threadIdx.x;
    const int tx = tid & 15, ty = tid >> 4;
    const int nb = blockIdx.x * 64;
    const int jt = blockIdx.y;
    const int b  = blockIdx.z;

    const float *wp, *bp; float *outp = 0;
    const int wsel = jt >> 1;
    if      (wsel == 0) { wp = th_w; bp = th_b; }
    else if (wsel == 1) { wp = ph_w; bp = ph_b; outp = g_Tphi; }
    else                { wp = gw;   bp = gb;   outp = g_Tg;   }
    const int j0 = (jt & 1) * 64;

    ull acc[4][4];
#pragma unroll
    for (int i = 0; i < 4; i++)
#pragma unroll
        for (int j = 0; j < 4; j++) acc[i][j] = 0ULL;

    const float* xb = x + (size_t)b * CIN * NSP;

    for (int kt = 0; kt < CIN / 16; kt++) {
        const int c0 = kt * 16;
        __syncthreads();
        {
            int idx = tid;
#pragma unroll
            for (int r = 0; r < 4; r++) {
                int cc = idx >> 6, nn = idx & 63;
                Xs[(cc >> 1) * 132 + nn * 2 + (cc & 1)] =
                    xb[(size_t)(c0 + cc) * NSP + nb + nn];
                idx += 256;
            }
        }
        {
            int idx = tid;
#pragma unroll
            for (int r = 0; r < 4; r++) {
                int jj = idx >> 4, cc = idx & 15;
                Ws[(cc >> 1) * 132 + jj * 2 + (cc & 1)] =
                    wp[(size_t)(j0 + jj) * CIN + c0 + cc];
                idx += 256;
            }
        }
        __syncthreads();
#pragma unroll
        for (int cp = 0; cp < 8; cp++) {
            ull a2[4], b2[4];
#pragma unroll
            for (int i = 0; i < 4; i++)
                a2[i] = *(const ull*)&Xs[cp * 132 + (ty * 4 + i) * 2];
#pragma unroll
            for (int j = 0; j < 4; j++)
                b2[j] = *(const ull*)&Ws[cp * 132 + (tx + 16 * j) * 2];
#pragma unroll
            for (int i = 0; i < 4; i++)
#pragma unroll
                for (int j = 0; j < 4; j++) fma2(acc[i][j], a2[i], b2[j]);
        }
    }
#pragma unroll
    for (int i = 0; i < 4; i++) {
        const int n = nb + ty * 4 + i;
#pragma unroll
        for (int j = 0; j < 4; j++) {
            const int c = j0 + tx + 16 * j;
            const float v = hsum2(acc[i][j]) + bp[c];
            const size_t o = ((size_t)b * NSP + n) * CI + c;
            if (wsel == 0) {
                __nv_bfloat16 h = __float2bfloat16(v);
                g_Qh[o] = h;
                g_Ql[o] = __float2bfloat16(v - __bfloat162float(h));
            } else {
                outp[o] = v;
            }
        }
    }
}

// ============================================================
// Kernel 2: 2x2 maxpool of phi/g -> bf16 hi/lo K and V, both (m, ci)
// ============================================================
__global__ void pool_kernel()
{
    const int bm = blockIdx.x;
    const int b = bm / MSP, m = bm % MSP;
    const int t = m / 196, rem = m % 196;
    const int h2 = rem / 14, w2 = rem % 14;
    const int n0 = t * 784 + (2 * h2) * 28 + 2 * w2;
    const int ci = threadIdx.x;
    const size_t base = (size_t)b * NSP * CI;
    const size_t o = ((size_t)b * MSP + m) * CI + ci;

    const float* p = g_Tphi;
    float pv = fmaxf(fmaxf(p[base + (size_t)n0 * CI + ci],
                           p[base + (size_t)(n0 + 1) * CI + ci]),
                     fmaxf(p[base + (size_t)(n0 + 28) * CI + ci],
                           p[base + (size_t)(n0 + 29) * CI + ci]));
    {
        __nv_bfloat16 h = __float2bfloat16(pv);
        g_Kh[o] = h;
        g_Kl[o] = __float2bfloat16(pv - __bfloat162float(h));
    }

    const float* gg = g_Tg;
    float gv = fmaxf(fmaxf(gg[base + (size_t)n0 * CI + ci],
                           gg[base + (size_t)(n0 + 1) * CI + ci]),
                     fmaxf(gg[base + (size_t)(n0 + 28) * CI + ci],
                           gg[base + (size_t)(n0 + 29) * CI + ci]));
    {
        __nv_bfloat16 h = __float2bfloat16(gv);
        g_Vh[o] = h;
        g_Vl[o] = __float2bfloat16(gv - __bfloat162float(h));
    }
}

// ============================================================
// Kernel 3: mma.sync flash attention, split-bf16 (hh+hl+lh), f32 accum.
// grid (49, 8), 256 threads (8 warps; warp owns 16 q-rows x full 128 cols).
// SMEM tiles Qh,Ql,Kh,Kl,Vh,Vl: 128 rows x 128 bf16, pitch 136 (ldmatrix
// conflict-free: 17x16B rows -> bankgroup r mod 8).
// ============================================================
#define PQ 136
#define TILE_BYTES (128 * PQ * 2)     // 34816
#define ATTN_SMEM  (6 * TILE_BYTES)   // 208896

__global__ __launch_bounds__(256) void attn_kernel()
{
    extern __shared__ __align__(16) char smem[];
    const int tid = threadIdx.x, lane = tid & 31, warp = tid >> 5;
    const int qb = blockIdx.x * 128, b = blockIdx.y;
    const uint32_t sb = smem_u32(smem);

    // ---- load Q tiles (persistent) ----
    {
        const __nv_bfloat16* gqh = g_Qh + ((size_t)b * NSP + qb) * CI;
        const __nv_bfloat16* gql = g_Ql + ((size_t)b * NSP + qb) * CI;
        for (int i = tid; i < 128 * 16; i += 256) {
            const int r = i >> 4, c8 = (i & 15) << 3;
            *(uint4*)(smem + (r * PQ + c8) * 2) =
                *(const uint4*)(gqh + (size_t)r * CI + c8);
            *(uint4*)(smem + TILE_BYTES + (r * PQ + c8) * 2) =
                *(const uint4*)(gql + (size_t)r * CI + c8);
        }
    }

    // ---- ldmatrix fragment base addresses ----
    // A (Q, non-trans): rows m = warp*16 + (lane&15), col8 = (lane>>4)
    const uint32_t aQH = sb + ((warp * 16 + (lane & 15)) * PQ + ((lane >> 4) << 3)) * 2;
    const uint32_t aQL = aQH + TILE_BYTES;
    // B (K, non-trans): rows n = (lane&7) + (lane>>4)*8, col8 = ((lane>>3)&1)
    const uint32_t kRow = (lane & 7) + ((lane >> 4) << 3);
    const uint32_t aKH = sb + 2 * TILE_BYTES + (kRow * PQ + (((lane >> 3) & 1) << 3)) * 2;
    const uint32_t aKL = aKH + TILE_BYTES;
    // B (V, trans): rows m = (lane&7) + ((lane>>3)&1)*8, col8 = (lane>>4)
    const uint32_t vRow = (lane & 7) + (((lane >> 3) & 1) << 3);
    const uint32_t aVH = sb + 4 * TILE_BYTES + (vRow * PQ + ((lane >> 4) << 3)) * 2;
    const uint32_t aVL = aVH + TILE_BYTES;

    float O[16][4];
#pragma unroll
    for (int t = 0; t < 16; t++)
#pragma unroll
        for (int j = 0; j < 4; j++) O[t][j] = 0.f;
    float m0 = -1e30f, m1 = -1e30f, l0 = 0.f, l1 = 0.f;

    for (int kt = 0; kt < 13; kt++) {
        const int kvb = kt * 128;
        const int kvn = (MSP - kvb) < 128 ? (MSP - kvb) : 128;

        __syncthreads();   // prior chunk's reads done (covers Q on kt=0)
        {
            const __nv_bfloat16* kh = g_Kh + ((size_t)b * MSP + kvb) * CI;
            const __nv_bfloat16* kl = g_Kl + ((size_t)b * MSP + kvb) * CI;
            const __nv_bfloat16* vh = g_Vh + ((size_t)b * MSP + kvb) * CI;
            const __nv_bfloat16* vl = g_Vl + ((size_t)b * MSP + kvb) * CI;
            for (int i = tid; i < kvn * 16; i += 256) {
                const int r = i >> 4, c8 = (i & 15) << 3;
                const size_t gsrc = (size_t)r * CI + c8;
                const int doff = (r * PQ + c8) * 2;
                *(uint4*)(smem + 2 * TILE_BYTES + doff) = *(const uint4*)(kh + gsrc);
                *(uint4*)(smem + 3 * TILE_BYTES + doff) = *(const uint4*)(kl + gsrc);
                *(uint4*)(smem + 4 * TILE_BYTES + doff) = *(const uint4*)(vh + gsrc);
                *(uint4*)(smem + 5 * TILE_BYTES + doff) = *(const uint4*)(vl + gsrc);
            }
        }
        __syncthreads();

        // ---- S = Qh Kh^T + Qh Kl^T + Ql Kh^T  (16 n8-tiles per warp) ----
        float S[16][4];
#pragma unroll
        for (int t = 0; t < 16; t++)
#pragma unroll
            for (int j = 0; j < 4; j++) S[t][j] = 0.f;

        for (int kk = 0; kk < 8; kk++) {
            uint32_t Ah[4], Al[4];
            ldsm4(Ah, aQH + kk * 32);
            ldsm4(Al, aQL + kk * 32);
#pragma unroll
            for (int g = 0; g < 8; g++) {
                uint32_t Bh[4], Bl[4];
                ldsm4(Bh, aKH + g * (16 * PQ * 2) + kk * 32);
                ldsm4(Bl, aKL + g * (16 * PQ * 2) + kk * 32);
                mma16816(S[2 * g],     Ah, Bh[0], Bh[1]);
                mma16816(S[2 * g + 1], Ah, Bh[2], Bh[3]);
                mma16816(S[2 * g],     Ah, Bl[0], Bl[1]);
                mma16816(S[2 * g + 1], Ah, Bl[2], Bl[3]);
                mma16816(S[2 * g],     Al, Bh[0], Bh[1]);
                mma16816(S[2 * g + 1], Al, Bh[2], Bh[3]);
            }
        }

        // ---- mask tail ----
        if (kvn < 128) {
#pragma unroll
            for (int t = 0; t < 16; t++) {
                const int c0 = t * 8 + (lane & 3) * 2;
                if (c0 >= kvn)     { S[t][0] = -1e30f; S[t][2] = -1e30f; }
                if (c0 + 1 >= kvn) { S[t][1] = -1e30f; S[t][3] = -1e30f; }
            }
        }

        // ---- online softmax (rows lane>>2 and +8; quad shuffles) ----
        float mx0 = -1e30f, mx1 = -1e30f;
#pragma unroll
        for (int t = 0; t < 16; t++) {
            mx0 = fmaxf(mx0, fmaxf(S[t][0], S[t][1]));
            mx1 = fmaxf(mx1, fmaxf(S[t][2], S[t][3]));
        }
        mx0 = fmaxf(mx0, __shfl_xor_sync(0xffffffffu, mx0, 1));
        mx0 = fmaxf(mx0, __shfl_xor_sync(0xffffffffu, mx0, 2));
        mx1 = fmaxf(mx1, __shfl_xor_sync(0xffffffffu, mx1, 1));
        mx1 = fmaxf(mx1, __shfl_xor_sync(0xffffffffu, mx1, 2));
        const float mn0 = fmaxf(m0, mx0), mn1 = fmaxf(m1, mx1);
        const float f0 = __expf(m0 - mn0), f1 = __expf(m1 - mn1);
        m0 = mn0; m1 = mn1;
        float s0 = 0.f, s1 = 0.f;
#pragma unroll
        for (int t = 0; t < 16; t++) {
            S[t][0] = __expf(S[t][0] - mn0); s0 += S[t][0];
            S[t][1] = __expf(S[t][1] - mn0); s0 += S[t][1];
            S[t][2] = __expf(S[t][2] - mn1); s1 += S[t][2];
            S[t][3] = __expf(S[t][3] - mn1); s1 += S[t][3];
        }
        s0 += __shfl_xor_sync(0xffffffffu, s0, 1);
        s0 += __shfl_xor_sync(0xffffffffu, s0, 2);
        s1 += __shfl_xor_sync(0xffffffffu, s1, 1);
        s1 += __shfl_xor_sync(0xffffffffu, s1, 2);
        l0 = l0 * f0 + s0;
        l1 = l1 * f1 + s1;
#pragma unroll
        for (int t = 0; t < 16; t++) {
            O[t][0] *= f0; O[t][1] *= f0; O[t][2] *= f1; O[t][3] *= f1;
        }

        // ---- P -> bf16 hi/lo A-fragments ----
        uint32_t Ph[8][4], Pl[8][4];
#pragma unroll
        for (int kk = 0; kk < 8; kk++) {
            const int t0 = 2 * kk, t1 = 2 * kk + 1;
#pragma unroll
            for (int q = 0; q < 4; q++) {
                const int tt = (q < 2) ? t0 : t1;
                const int j0 = (q & 1) * 2;
                const float p0 = S[tt][j0], p1 = S[tt][j0 + 1];
                __nv_bfloat162 h2 = __floats2bfloat162_rn(p0, p1);
                Ph[kk][q] = *(uint32_t*)&h2;
                __nv_bfloat162 l2 = __floats2bfloat162_rn(
                    p0 - __bfloat162float(h2.x), p1 - __bfloat162float(h2.y));
                Pl[kk][q] = *(uint32_t*)&l2;
            }
        }

        // ---- O += Ph Vh + Ph Vl + Pl Vh ----
#pragma unroll
        for (int kk = 0; kk < 8; kk++) {
#pragma unroll
            for (int g = 0; g < 8; g++) {
                uint32_t Vh4[4], Vl4[4];
                ldsm4t(Vh4, aVH + kk * (16 * PQ * 2) + g * 32);
                ldsm4t(Vl4, aVL + kk * (16 * PQ * 2) + g * 32);
                mma16816(O[2 * g],     Ph[kk], Vh4[0], Vh4[1]);
                mma16816(O[2 * g + 1], Ph[kk], Vh4[2], Vh4[3]);
                mma16816(O[2 * g],     Ph[kk], Vl4[0], Vl4[1]);
                mma16816(O[2 * g + 1], Ph[kk], Vl4[2], Vl4[3]);
                mma16816(O[2 * g],     Pl[kk], Vh4[0], Vh4[1]);
                mma16816(O[2 * g + 1], Pl[kk], Vh4[2], Vh4[3]);
            }
        }
    }

    // ---- y = O / l ----
    {
        const float inv0 = 1.0f / l0, inv1 = 1.0f / l1;
        const int r0 = qb + warp * 16 + (lane >> 2);
        float* y0 = g_Y + ((size_t)b * NSP + r0) * CI + (lane & 3) * 2;
        float* y1 = y0 + 8 * CI;
#pragma unroll
        for (int t = 0; t < 16; t++) {
            *(float2*)(y0 + t * 8) = make_float2(O[t][0] * inv0, O[t][1] * inv0);
            *(float2*)(y1 + t * 8) = make_float2(O[t][2] * inv1, O[t][3] * inv1);
        }
    }
}

// ============================================================
// Kernel 4: out = W*y + b + x  (f32x2 SGEMM)
// ============================================================
__global__ __launch_bounds__(256) void out_kernel(
    const float* __restrict__ x,
    const float* __restrict__ Ww, const float* __restrict__ Wb,
    float* __restrict__ out)
{
    __shared__ __align__(16) float Ys[8 * 132];
    __shared__ __align__(16) float Ws[8 * 132];

    const int tid = threadIdx.x;
    const int tx = tid & 15, ty = tid >> 4;
    const int nb  = blockIdx.x * 64;
    const int co0 = blockIdx.y * 64;
    const int b   = blockIdx.z;

    ull acc[4][4];
#pragma unroll
    for (int i = 0; i < 4; i++)
#pragma unroll
        for (int j = 0; j < 4; j++) acc[i][j] = 0ULL;

    const float* yb = g_Y + (size_t)b * NSP * CI;

    for (int kt = 0; kt < CI / 16; kt++) {
        const int c0 = kt * 16;
        __syncthreads();
        {
            int idx = tid;
#pragma unroll
            for (int r = 0; r < 4; r++) {
                int nn = idx >> 4, cc = idx & 15;
                Ys[(cc >> 1) * 132 + nn * 2 + (cc & 1)] =
                    yb[(size_t)(nb + nn) * CI + c0 + cc];
                idx += 256;
            }
        }
        {
            int idx = tid;
#pragma unroll
            for (int r = 0; r < 4; r++) {
                int jj = idx >> 4, cc = idx & 15;
                Ws[(cc >> 1) * 132 + jj * 2 + (cc & 1)] =
                    Ww[(size_t)(co0 + jj) * CI + c0 + cc];
                idx += 256;
            }
        }
        __syncthreads();
#pragma unroll
        for (int cp = 0; cp < 8; cp++) {
            ull a2[4], b2[4];
#pragma unroll
            for (int i = 0; i < 4; i++)
                a2[i] = *(const ull*)&Ws[cp * 132 + (ty * 4 + i) * 2];
#pragma unroll
            for (int j = 0; j < 4; j++)
                b2[j] = *(const ull*)&Ys[cp * 132 + (tx + 16 * j) * 2];
#pragma unroll
            for (int i = 0; i < 4; i++)
#pragma unroll
                for (int j = 0; j < 4; j++) fma2(acc[i][j], a2[i], b2[j]);
        }
    }
#pragma unroll
    for (int i = 0; i < 4; i++) {
        const int co = co0 + ty * 4 + i;
        const float bias = Wb[co];
        const float* xr  = x   + ((size_t)b * CIN + co) * NSP;
        float*      orow = out + ((size_t)b * CIN + co) * NSP;
#pragma unroll
        for (int j = 0; j < 4; j++) {
            const int n = nb + tx + 16 * j;
            orow[n] = hsum2(acc[i][j]) + bias + xr[n];
        }
    }
}

// ============================================================
extern "C" void kernel_launch(void* const* d_in, const int* in_sizes, int n_in,
                              void* d_out, int out_size)
{
    const float* x    = (const float*)d_in[0];
    const float* g_w  = (const float*)d_in[1];
    const float* g_b  = (const float*)d_in[2];
    const float* th_w = (const float*)d_in[3];
    const float* th_b = (const float*)d_in[4];
    const float* ph_w = (const float*)d_in[5];
    const float* ph_b = (const float*)d_in[6];
    const float* W_w  = (const float*)d_in[7];
    const float* W_b  = (const float*)d_in[8];
    float* out = (float*)d_out;

    cudaFuncSetAttribute(attn_kernel,
                         cudaFuncAttributeMaxDynamicSharedMemorySize, ATTN_SMEM);

    dim3 g1(NSP / 64, 6, BATCH);
    proj_kernel<<<g1, 256>>>(x, th_w, th_b, ph_w, ph_b, g_w, g_b);

    pool_kernel<<<BATCH * MSP, 128>>>();

    dim3 g2(NSP / 128, BATCH);
    attn_kernel<<<g2, 256, ATTN_SMEM>>>();

    dim3 g3(NSP / 64, CIN / 64, BATCH);
    out_kernel<<<g3, 256>>>(x, W_w, W_b, out);
}

// round 5
// speedup vs baseline: 3.2665x; 1.2756x over previous
#include <cuda_runtime.h>
#include <cuda_bf16.h>
#include <cstdint>
#include <math.h>

#define BATCH 8
#define CIN   256
#define CI    128
#define NSP   6272   // 8*28*28
#define MSP   1568   // 8*14*14

// ---- scratch (static device arrays; allocation-free) ----
__device__ float g_Tphi[BATCH * NSP * CI];
__device__ float g_Tg  [BATCH * NSP * CI];
__device__ __nv_bfloat16 g_Qh[BATCH * NSP * CI];
__device__ __nv_bfloat16 g_Ql[BATCH * NSP * CI];
__device__ __nv_bfloat16 g_Kh[BATCH * MSP * CI];
__device__ __nv_bfloat16 g_Kl[BATCH * MSP * CI];
__device__ __nv_bfloat16 g_Vh[BATCH * MSP * CI];
__device__ __nv_bfloat16 g_Vl[BATCH * MSP * CI];
__device__ __nv_bfloat16 g_Yh[BATCH * NSP * CI];
__device__ __nv_bfloat16 g_Yl[BATCH * NSP * CI];

__device__ __forceinline__ uint32_t smem_u32(const void* p) {
    uint32_t a;
    asm("{ .reg .u64 t; cvta.to.shared.u64 t, %1; cvt.u32.u64 %0, t; }"
        : "=r"(a) : "l"(p));
    return a;
}

// ---- mma.sync helpers (sm_80 baseline ISA; compiles under compute_103) ----
__device__ __forceinline__ void ldsm4(uint32_t (&r)[4], uint32_t addr) {
    asm volatile("ldmatrix.sync.aligned.m8n8.x4.shared.b16 {%0,%1,%2,%3}, [%4];"
        : "=r"(r[0]), "=r"(r[1]), "=r"(r[2]), "=r"(r[3]) : "r"(addr));
}
__device__ __forceinline__ void ldsm4t(uint32_t (&r)[4], uint32_t addr) {
    asm volatile("ldmatrix.sync.aligned.m8n8.x4.trans.shared.b16 {%0,%1,%2,%3}, [%4];"
        : "=r"(r[0]), "=r"(r[1]), "=r"(r[2]), "=r"(r[3]) : "r"(addr));
}
__device__ __forceinline__ void mma16816(float (&d)[4], const uint32_t (&a)[4],
                                         uint32_t b0, uint32_t b1) {
    asm volatile("mma.sync.aligned.m16n8k16.row.col.f32.bf16.bf16.f32 "
        "{%0,%1,%2,%3}, {%4,%5,%6,%7}, {%8,%9}, {%0,%1,%2,%3};"
        : "+f"(d[0]), "+f"(d[1]), "+f"(d[2]), "+f"(d[3])
        : "r"(a[0]), "r"(a[1]), "r"(a[2]), "r"(a[3]), "r"(b0), "r"(b1));
}

// ============================================================
// Kernel 1: fused projections via split-bf16 mma.sync.
// grid (49, 8), 256 threads. Per CTA: 128 n-rows, all 3 projections.
// Computes out^T: A = W[j,c] (ldsm non-trans), B = x[c,n] (ldsm trans).
// theta -> split bf16 (g_Qh/Ql); phi/g -> f32 (g_Tphi/g_Tg) for pooling.
// SMEM: Xh/Xl (256c x 128n, pitch 136) + union{ W chunk hi/lo | staging }.
// ============================================================
#define PX 136
#define PW 72
#define PS 136
#define PF 132
#define OFF_XH 0
#define OFF_XL 69632
#define OFF_U  139264
#define W_LO_OFF 18432            // 128*72*2
#define PROJ_SMEM (139264 + 67584)  // 206848

__global__ __launch_bounds__(256) void proj_kernel(
    const float* __restrict__ x,
    const float* __restrict__ th_w, const float* __restrict__ th_b,
    const float* __restrict__ ph_w, const float* __restrict__ ph_b,
    const float* __restrict__ gw,   const float* __restrict__ gb)
{
    extern __shared__ __align__(16) char ps[];
    const int tid = threadIdx.x, lane = tid & 31, warp = tid >> 5;
    const int nb = blockIdx.x * 128, b = blockIdx.y;
    const uint32_t sb = smem_u32(ps);

    // ---- load + split X tile (256 c-rows x 128 n-cols) ----
    const float* xb = x + (size_t)b * CIN * NSP + nb;
    for (int i = tid; i < 256 * 32; i += 256) {
        const int c = i >> 5, n4 = (i & 31) << 2;
        float4 v = *(const float4*)(xb + (size_t)c * NSP + n4);
        __nv_bfloat162 h01 = __floats2bfloat162_rn(v.x, v.y);
        __nv_bfloat162 h23 = __floats2bfloat162_rn(v.z, v.w);
        *(__nv_bfloat162*)(ps + OFF_XH + (c * PX + n4) * 2)     = h01;
        *(__nv_bfloat162*)(ps + OFF_XH + (c * PX + n4) * 2 + 4) = h23;
        __nv_bfloat162 l01 = __floats2bfloat162_rn(v.x - __bfloat162float(h01.x),
                                                   v.y - __bfloat162float(h01.y));
        __nv_bfloat162 l23 = __floats2bfloat162_rn(v.z - __bfloat162float(h23.x),
                                                   v.w - __bfloat162float(h23.y));
        *(__nv_bfloat162*)(ps + OFF_XL + (c * PX + n4) * 2)     = l01;
        *(__nv_bfloat162*)(ps + OFF_XL + (c * PX + n4) * 2 + 4) = l23;
    }

    // fragment base addresses
    const uint32_t aW = sb + OFF_U + ((warp * 16 + (lane & 15)) * PW + ((lane >> 4) << 3)) * 2;
    const uint32_t xRow = (lane & 7) + (((lane >> 3) & 1) << 3);
    const uint32_t aX = sb + OFF_XH + (xRow * PX + ((lane >> 4) << 3)) * 2;

    const int j0 = warp * 16 + (lane >> 2), j1 = j0 + 8;

    for (int p = 0; p < 3; p++) {
        const float* wp = (p == 0) ? th_w : (p == 1) ? ph_w : gw;
        const float* bp = (p == 0) ? th_b : (p == 1) ? ph_b : gb;

        float D[16][4];
#pragma unroll
        for (int t = 0; t < 16; t++)
#pragma unroll
            for (int j = 0; j < 4; j++) D[t][j] = 0.f;

        for (int chunk = 0; chunk < 4; chunk++) {
            __syncthreads();   // U region free (prior mma / staging reads done)
            // load + split W chunk (128 j x 64 c)
            for (int i = tid; i < 128 * 16; i += 256) {
                const int j = i >> 4, c4 = (i & 15) << 2;
                float4 w = *(const float4*)(wp + (size_t)j * CIN + chunk * 64 + c4);
                __nv_bfloat162 h01 = __floats2bfloat162_rn(w.x, w.y);
                __nv_bfloat162 h23 = __floats2bfloat162_rn(w.z, w.w);
                *(__nv_bfloat162*)(ps + OFF_U + (j * PW + c4) * 2)     = h01;
                *(__nv_bfloat162*)(ps + OFF_U + (j * PW + c4) * 2 + 4) = h23;
                __nv_bfloat162 l01 = __floats2bfloat162_rn(w.x - __bfloat162float(h01.x),
                                                           w.y - __bfloat162float(h01.y));
                __nv_bfloat162 l23 = __floats2bfloat162_rn(w.z - __bfloat162float(h23.x),
                                                           w.w - __bfloat162float(h23.y));
                *(__nv_bfloat162*)(ps + OFF_U + W_LO_OFF + (j * PW + c4) * 2)     = l01;
                *(__nv_bfloat162*)(ps + OFF_U + W_LO_OFF + (j * PW + c4) * 2 + 4) = l23;
            }
            __syncthreads();
#pragma unroll
            for (int kk2 = 0; kk2 < 4; kk2++) {
                uint32_t Ah[4], Al[4];
                ldsm4(Ah, aW + kk2 * 32);
                ldsm4(Al, aW + W_LO_OFF + kk2 * 32);
                const uint32_t xoff = (chunk * 4 + kk2) * (16 * PX * 2);
#pragma unroll
                for (int g = 0; g < 8; g++) {
                    uint32_t Bh[4], Bl[4];
                    ldsm4t(Bh, aX + xoff + g * 32);
                    ldsm4t(Bl, aX + (OFF_XL - OFF_XH) + xoff + g * 32);
                    mma16816(D[2 * g],     Ah, Bh[0], Bh[1]);
                    mma16816(D[2 * g + 1], Ah, Bh[2], Bh[3]);
                    mma16816(D[2 * g],     Ah, Bl[0], Bl[1]);
                    mma16816(D[2 * g + 1], Ah, Bl[2], Bl[3]);
                    mma16816(D[2 * g],     Al, Bh[0], Bh[1]);
                    mma16816(D[2 * g + 1], Al, Bh[2], Bh[3]);
                }
            }
        }
        __syncthreads();   // all warps done reading W region

        const float bias0 = bp[j0], bias1 = bp[j1];
        if (p == 0) {
            // theta: split bf16, staged transpose, two passes (hi then lo)
            __nv_bfloat16* dsth = g_Qh + ((size_t)b * NSP + nb) * CI;
            __nv_bfloat16* dstl = g_Ql + ((size_t)b * NSP + nb) * CI;
#pragma unroll
            for (int t = 0; t < 16; t++) {
                const int n = t * 8 + (lane & 3) * 2;
                *(__nv_bfloat16*)(ps + OFF_U + (n * PS + j0) * 2)       = __float2bfloat16(D[t][0] + bias0);
                *(__nv_bfloat16*)(ps + OFF_U + ((n + 1) * PS + j0) * 2) = __float2bfloat16(D[t][1] + bias0);
                *(__nv_bfloat16*)(ps + OFF_U + (n * PS + j1) * 2)       = __float2bfloat16(D[t][2] + bias1);
                *(__nv_bfloat16*)(ps + OFF_U + ((n + 1) * PS + j1) * 2) = __float2bfloat16(D[t][3] + bias1);
            }
            __syncthreads();
            for (int i = tid; i < 128 * 16; i += 256) {
                const int n = i >> 4, j8 = (i & 15) << 3;
                *(uint4*)(dsth + (size_t)n * CI + j8) =
                    *(const uint4*)(ps + OFF_U + (n * PS + j8) * 2);
            }
            __syncthreads();
#pragma unroll
            for (int t = 0; t < 16; t++) {
                const int n = t * 8 + (lane & 3) * 2;
                const float v0 = D[t][0] + bias0, v1 = D[t][1] + bias0;
                const float v2 = D[t][2] + bias1, v3 = D[t][3] + bias1;
                *(__nv_bfloat16*)(ps + OFF_U + (n * PS + j0) * 2) =
                    __float2bfloat16(v0 - __bfloat162float(__float2bfloat16(v0)));
                *(__nv_bfloat16*)(ps + OFF_U + ((n + 1) * PS + j0) * 2) =
                    __float2bfloat16(v1 - __bfloat162float(__float2bfloat16(v1)));
                *(__nv_bfloat16*)(ps + OFF_U + (n * PS + j1) * 2) =
                    __float2bfloat16(v2 - __bfloat162float(__float2bfloat16(v2)));
                *(__nv_bfloat16*)(ps + OFF_U + ((n + 1) * PS + j1) * 2) =
                    __float2bfloat16(v3 - __bfloat162float(__float2bfloat16(v3)));
            }
            __syncthreads();
            for (int i = tid; i < 128 * 16; i += 256) {
                const int n = i >> 4, j8 = (i & 15) << 3;
                *(uint4*)(dstl + (size_t)n * CI + j8) =
                    *(const uint4*)(ps + OFF_U + (n * PS + j8) * 2);
            }
        } else {
            // phi / g: f32 staged transpose (pooled+split later)
            float* dst = ((p == 1) ? g_Tphi : g_Tg) + ((size_t)b * NSP + nb) * CI;
#pragma unroll
            for (int t = 0; t < 16; t++) {
                const int n = t * 8 + (lane & 3) * 2;
                *(float*)(ps + OFF_U + (n * PF + j0) * 4)       = D[t][0] + bias0;
                *(float*)(ps + OFF_U + ((n + 1) * PF + j0) * 4) = D[t][1] + bias0;
                *(float*)(ps + OFF_U + (n * PF + j1) * 4)       = D[t][2] + bias1;
                *(float*)(ps + OFF_U + ((n + 1) * PF + j1) * 4) = D[t][3] + bias1;
            }
            __syncthreads();
            for (int i = tid; i < 128 * 32; i += 256) {
                const int n = i >> 5, j4 = (i & 31) << 2;
                *(float4*)(dst + (size_t)n * CI + j4) =
                    *(const float4*)(ps + OFF_U + (n * PF + j4) * 4);
            }
        }
    }
}

// ============================================================
// Kernel 2: 2x2 maxpool of phi/g -> bf16 hi/lo K and V, both (m, ci)
// ============================================================
__global__ void pool_kernel()
{
    const int bm = blockIdx.x;
    const int b = bm / MSP, m = bm % MSP;
    const int t = m / 196, rem = m % 196;
    const int h2 = rem / 14, w2 = rem % 14;
    const int n0 = t * 784 + (2 * h2) * 28 + 2 * w2;
    const int ci = threadIdx.x;
    const size_t base = (size_t)b * NSP * CI;
    const size_t o = ((size_t)b * MSP + m) * CI + ci;

    const float* p = g_Tphi;
    float pv = fmaxf(fmaxf(p[base + (size_t)n0 * CI + ci],
                           p[base + (size_t)(n0 + 1) * CI + ci]),
                     fmaxf(p[base + (size_t)(n0 + 28) * CI + ci],
                           p[base + (size_t)(n0 + 29) * CI + ci]));
    {
        __nv_bfloat16 h = __float2bfloat16(pv);
        g_Kh[o] = h;
        g_Kl[o] = __float2bfloat16(pv - __bfloat162float(h));
    }

    const float* gg = g_Tg;
    float gv = fmaxf(fmaxf(gg[base + (size_t)n0 * CI + ci],
                           gg[base + (size_t)(n0 + 1) * CI + ci]),
                     fmaxf(gg[base + (size_t)(n0 + 28) * CI + ci],
                           gg[base + (size_t)(n0 + 29) * CI + ci]));
    {
        __nv_bfloat16 h = __float2bfloat16(gv);
        g_Vh[o] = h;
        g_Vl[o] = __float2bfloat16(gv - __bfloat162float(h));
    }
}

// ============================================================
// Kernel 3: mma.sync flash attention, split-bf16 (hh+hl+lh), f32 accum.
// grid (49, 8), 256 threads (8 warps; warp owns 16 q-rows x full 128 cols).
// Epilogue writes y pre-split to bf16 hi/lo (g_Yh/g_Yl) for out_kernel.
// ============================================================
#define PQ 136
#define TILE_BYTES (128 * PQ * 2)     // 34816
#define ATTN_SMEM  (6 * TILE_BYTES)   // 208896

__global__ __launch_bounds__(256) void attn_kernel()
{
    extern __shared__ __align__(16) char smem[];
    const int tid = threadIdx.x, lane = tid & 31, warp = tid >> 5;
    const int qb = blockIdx.x * 128, b = blockIdx.y;
    const uint32_t sb = smem_u32(smem);

    // ---- load Q tiles (persistent) ----
    {
        const __nv_bfloat16* gqh = g_Qh + ((size_t)b * NSP + qb) * CI;
        const __nv_bfloat16* gql = g_Ql + ((size_t)b * NSP + qb) * CI;
        for (int i = tid; i < 128 * 16; i += 256) {
            const int r = i >> 4, c8 = (i & 15) << 3;
            *(uint4*)(smem + (r * PQ + c8) * 2) =
                *(const uint4*)(gqh + (size_t)r * CI + c8);
            *(uint4*)(smem + TILE_BYTES + (r * PQ + c8) * 2) =
                *(const uint4*)(gql + (size_t)r * CI + c8);
        }
    }

    const uint32_t aQH = sb + ((warp * 16 + (lane & 15)) * PQ + ((lane >> 4) << 3)) * 2;
    const uint32_t aQL = aQH + TILE_BYTES;
    const uint32_t kRow = (lane & 7) + ((lane >> 4) << 3);
    const uint32_t aKH = sb + 2 * TILE_BYTES + (kRow * PQ + (((lane >> 3) & 1) << 3)) * 2;
    const uint32_t aKL = aKH + TILE_BYTES;
    const uint32_t vRow = (lane & 7) + (((lane >> 3) & 1) << 3);
    const uint32_t aVH = sb + 4 * TILE_BYTES + (vRow * PQ + ((lane >> 4) << 3)) * 2;
    const uint32_t aVL = aVH + TILE_BYTES;

    float O[16][4];
#pragma unroll
    for (int t = 0; t < 16; t++)
#pragma unroll
        for (int j = 0; j < 4; j++) O[t][j] = 0.f;
    float m0 = -1e30f, m1 = -1e30f, l0 = 0.f, l1 = 0.f;

    for (int kt = 0; kt < 13; kt++) {
        const int kvb = kt * 128;
        const int kvn = (MSP - kvb) < 128 ? (MSP - kvb) : 128;

        __syncthreads();
        {
            const __nv_bfloat16* kh = g_Kh + ((size_t)b * MSP + kvb) * CI;
            const __nv_bfloat16* kl = g_Kl + ((size_t)b * MSP + kvb) * CI;
            const __nv_bfloat16* vh = g_Vh + ((size_t)b * MSP + kvb) * CI;
            const __nv_bfloat16* vl = g_Vl + ((size_t)b * MSP + kvb) * CI;
            for (int i = tid; i < kvn * 16; i += 256) {
                const int r = i >> 4, c8 = (i & 15) << 3;
                const size_t gsrc = (size_t)r * CI + c8;
                const int doff = (r * PQ + c8) * 2;
                *(uint4*)(smem + 2 * TILE_BYTES + doff) = *(const uint4*)(kh + gsrc);
                *(uint4*)(smem + 3 * TILE_BYTES + doff) = *(const uint4*)(kl + gsrc);
                *(uint4*)(smem + 4 * TILE_BYTES + doff) = *(const uint4*)(vh + gsrc);
                *(uint4*)(smem + 5 * TILE_BYTES + doff) = *(const uint4*)(vl + gsrc);
            }
        }
        __syncthreads();

        // ---- S = Qh Kh^T + Qh Kl^T + Ql Kh^T ----
        float S[16][4];
#pragma unroll
        for (int t = 0; t < 16; t++)
#pragma unroll
            for (int j = 0; j < 4; j++) S[t][j] = 0.f;

        for (int kk = 0; kk < 8; kk++) {
            uint32_t Ah[4], Al[4];
            ldsm4(Ah, aQH + kk * 32);
            ldsm4(Al, aQL + kk * 32);
#pragma unroll
            for (int g = 0; g < 8; g++) {
                uint32_t Bh[4], Bl[4];
                ldsm4(Bh, aKH + g * (16 * PQ * 2) + kk * 32);
                ldsm4(Bl, aKL + g * (16 * PQ * 2) + kk * 32);
                mma16816(S[2 * g],     Ah, Bh[0], Bh[1]);
                mma16816(S[2 * g + 1], Ah, Bh[2], Bh[3]);
                mma16816(S[2 * g],     Ah, Bl[0], Bl[1]);
                mma16816(S[2 * g + 1], Ah, Bl[2], Bl[3]);
                mma16816(S[2 * g],     Al, Bh[0], Bh[1]);
                mma16816(S[2 * g + 1], Al, Bh[2], Bh[3]);
            }
        }

        if (kvn < 128) {
#pragma unroll
            for (int t = 0; t < 16; t++) {
                const int c0 = t * 8 + (lane & 3) * 2;
                if (c0 >= kvn)     { S[t][0] = -1e30f; S[t][2] = -1e30f; }
                if (c0 + 1 >= kvn) { S[t][1] = -1e30f; S[t][3] = -1e30f; }
            }
        }

        // ---- online softmax ----
        float mx0 = -1e30f, mx1 = -1e30f;
#pragma unroll
        for (int t = 0; t < 16; t++) {
            mx0 = fmaxf(mx0, fmaxf(S[t][0], S[t][1]));
            mx1 = fmaxf(mx1, fmaxf(S[t][2], S[t][3]));
        }
        mx0 = fmaxf(mx0, __shfl_xor_sync(0xffffffffu, mx0, 1));
        mx0 = fmaxf(mx0, __shfl_xor_sync(0xffffffffu, mx0, 2));
        mx1 = fmaxf(mx1, __shfl_xor_sync(0xffffffffu, mx1, 1));
        mx1 = fmaxf(mx1, __shfl_xor_sync(0xffffffffu, mx1, 2));
        const float mn0 = fmaxf(m0, mx0), mn1 = fmaxf(m1, mx1);
        const float f0 = __expf(m0 - mn0), f1 = __expf(m1 - mn1);
        m0 = mn0; m1 = mn1;
        float s0 = 0.f, s1 = 0.f;
#pragma unroll
        for (int t = 0; t < 16; t++) {
            S[t][0] = __expf(S[t][0] - mn0); s0 += S[t][0];
            S[t][1] = __expf(S[t][1] - mn0); s0 += S[t][1];
            S[t][2] = __expf(S[t][2] - mn1); s1 += S[t][2];
            S[t][3] = __expf(S[t][3] - mn1); s1 += S[t][3];
        }
        s0 += __shfl_xor_sync(0xffffffffu, s0, 1);
        s0 += __shfl_xor_sync(0xffffffffu, s0, 2);
        s1 += __shfl_xor_sync(0xffffffffu, s1, 1);
        s1 += __shfl_xor_sync(0xffffffffu, s1, 2);
        l0 = l0 * f0 + s0;
        l1 = l1 * f1 + s1;
#pragma unroll
        for (int t = 0; t < 16; t++) {
            O[t][0] *= f0; O[t][1] *= f0; O[t][2] *= f1; O[t][3] *= f1;
        }

        // ---- P -> bf16 hi/lo A-fragments ----
        uint32_t Ph[8][4], Pl[8][4];
#pragma unroll
        for (int kk = 0; kk < 8; kk++) {
            const int t0 = 2 * kk, t1 = 2 * kk + 1;
#pragma unroll
            for (int q = 0; q < 4; q++) {
                const int tt = (q < 2) ? t0 : t1;
                const int jj = (q & 1) * 2;
                const float p0 = S[tt][jj], p1 = S[tt][jj + 1];
                __nv_bfloat162 h2 = __floats2bfloat162_rn(p0, p1);
                Ph[kk][q] = *(uint32_t*)&h2;
                __nv_bfloat162 l2 = __floats2bfloat162_rn(
                    p0 - __bfloat162float(h2.x), p1 - __bfloat162float(h2.y));
                Pl[kk][q] = *(uint32_t*)&l2;
            }
        }

        // ---- O += Ph Vh + Ph Vl + Pl Vh ----
#pragma unroll
        for (int kk = 0; kk < 8; kk++) {
#pragma unroll
            for (int g = 0; g < 8; g++) {
                uint32_t Vh4[4], Vl4[4];
                ldsm4t(Vh4, aVH + kk * (16 * PQ * 2) + g * 32);
                ldsm4t(Vl4, aVL + kk * (16 * PQ * 2) + g * 32);
                mma16816(O[2 * g],     Ph[kk], Vh4[0], Vh4[1]);
                mma16816(O[2 * g + 1], Ph[kk], Vh4[2], Vh4[3]);
                mma16816(O[2 * g],     Ph[kk], Vl4[0], Vl4[1]);
                mma16816(O[2 * g + 1], Ph[kk], Vl4[2], Vl4[3]);
                mma16816(O[2 * g],     Pl[kk], Vh4[0], Vh4[1]);
                mma16816(O[2 * g + 1], Pl[kk], Vh4[2], Vh4[3]);
            }
        }
    }

    // ---- y = O / l, written pre-split to bf16 hi/lo ----
    {
        const float inv0 = 1.0f / l0, inv1 = 1.0f / l1;
        const int r0 = qb + warp * 16 + (lane >> 2);
        const size_t base0 = ((size_t)b * NSP + r0) * CI + (lane & 3) * 2;
        const size_t base1 = base0 + 8 * CI;
#pragma unroll
        for (int t = 0; t < 16; t++) {
            const float v0 = O[t][0] * inv0, v1 = O[t][1] * inv0;
            __nv_bfloat162 h = __floats2bfloat162_rn(v0, v1);
            *(__nv_bfloat162*)(g_Yh + base0 + t * 8) = h;
            *(__nv_bfloat162*)(g_Yl + base0 + t * 8) = __floats2bfloat162_rn(
                v0 - __bfloat162float(h.x), v1 - __bfloat162float(h.y));
            const float w0 = O[t][2] * inv1, w1 = O[t][3] * inv1;
            __nv_bfloat162 h2 = __floats2bfloat162_rn(w0, w1);
            *(__nv_bfloat162*)(g_Yh + base1 + t * 8) = h2;
            *(__nv_bfloat162*)(g_Yl + base1 + t * 8) = __floats2bfloat162_rn(
                w0 - __bfloat162float(h2.x), w1 - __bfloat162float(h2.y));
        }
    }
}

// ============================================================
// Kernel 4: out = W*y + b + x via split-bf16 mma.sync.
// grid (49, 2, 8), 256 threads. A = W_w[co,ci] split, B = y[n,ci] split.
// D = (co, n): direct coalesced float2 writes with bias + residual.
// ============================================================
#define OW_WH 0
#define OW_WL 34816
#define OW_YH 69632
#define OW_YL 104448
#define OUT_SMEM 139264

__global__ __launch_bounds__(256) void out_kernel(
    const float* __restrict__ x,
    const float* __restrict__ Ww, const float* __restrict__ Wb,
    float* __restrict__ out)
{
    extern __shared__ __align__(16) char ps[];
    const int tid = threadIdx.x, lane = tid & 31, warp = tid >> 5;
    const int nb = blockIdx.x * 128, co0 = blockIdx.y * 128, b = blockIdx.z;
    const uint32_t sb = smem_u32(ps);

    // load + split W tile (128 co x 128 ci)
    for (int i = tid; i < 128 * 32; i += 256) {
        const int co = i >> 5, c4 = (i & 31) << 2;
        float4 w = *(const float4*)(Ww + (size_t)(co0 + co) * CI + c4);
        __nv_bfloat162 h01 = __floats2bfloat162_rn(w.x, w.y);
        __nv_bfloat162 h23 = __floats2bfloat162_rn(w.z, w.w);
        *(__nv_bfloat162*)(ps + OW_WH + (co * 136 + c4) * 2)     = h01;
        *(__nv_bfloat162*)(ps + OW_WH + (co * 136 + c4) * 2 + 4) = h23;
        __nv_bfloat162 l01 = __floats2bfloat162_rn(w.x - __bfloat162float(h01.x),
                                                   w.y - __bfloat162float(h01.y));
        __nv_bfloat162 l23 = __floats2bfloat162_rn(w.z - __bfloat162float(h23.x),
                                                   w.w - __bfloat162float(h23.y));
        *(__nv_bfloat162*)(ps + OW_WL + (co * 136 + c4) * 2)     = l01;
        *(__nv_bfloat162*)(ps + OW_WL + (co * 136 + c4) * 2 + 4) = l23;
    }
    // load Y tiles (already split)
    {
        const __nv_bfloat16* yh = g_Yh + ((size_t)b * NSP + nb) * CI;
        const __nv_bfloat16* yl = g_Yl + ((size_t)b * NSP + nb) * CI;
        for (int i = tid; i < 128 * 16; i += 256) {
            const int n = i >> 4, c8 = (i & 15) << 3;
            *(uint4*)(ps + OW_YH + (n * 136 + c8) * 2) = *(const uint4*)(yh + (size_t)n * CI + c8);
            *(uint4*)(ps + OW_YL + (n * 136 + c8) * 2) = *(const uint4*)(yl + (size_t)n * CI + c8);
        }
    }
    __syncthreads();

    float D[16][4];
#pragma unroll
    for (int t = 0; t < 16; t++)
#pragma unroll
        for (int j = 0; j < 4; j++) D[t][j] = 0.f;

    const uint32_t aW = sb + OW_WH + ((warp * 16 + (lane & 15)) * 136 + ((lane >> 4) << 3)) * 2;
    const uint32_t kRow = (lane & 7) + ((lane >> 4) << 3);
    const uint32_t aY = sb + OW_YH + (kRow * 136 + (((lane >> 3) & 1) << 3)) * 2;

    for (int kk = 0; kk < 8; kk++) {
        uint32_t Ah[4], Al[4];
        ldsm4(Ah, aW + kk * 32);
        ldsm4(Al, aW + (OW_WL - OW_WH) + kk * 32);
#pragma unroll
        for (int g = 0; g < 8; g++) {
            uint32_t Bh[4], Bl[4];
            ldsm4(Bh, aY + g * (16 * 136 * 2) + kk * 32);
            ldsm4(Bl, aY + (OW_YL - OW_YH) + g * (16 * 136 * 2) + kk * 32);
            mma16816(D[2 * g],     Ah, Bh[0], Bh[1]);
            mma16816(D[2 * g + 1], Ah, Bh[2], Bh[3]);
            mma16816(D[2 * g],     Ah, Bl[0], Bl[1]);
            mma16816(D[2 * g + 1], Ah, Bl[2], Bl[3]);
            mma16816(D[2 * g],     Al, Bh[0], Bh[1]);
            mma16816(D[2 * g + 1], Al, Bh[2], Bh[3]);
        }
    }

    // epilogue: bias + residual, direct float2 writes
    const int co = co0 + warp * 16 + (lane >> 2);
    const float bias0 = Wb[co], bias1 = Wb[co + 8];
    const float* xr0 = x + ((size_t)b * CIN + co) * NSP + nb;
    const float* xr1 = xr0 + (size_t)8 * NSP;
    float* o0 = out + ((size_t)b * CIN + co) * NSP + nb;
    float* o1 = o0 + (size_t)8 * NSP;
#pragma unroll
    for (int t = 0; t < 16; t++) {
        const int n = t * 8 + (lane & 3) * 2;
        const float2 xv0 = *(const float2*)(xr0 + n);
        *(float2*)(o0 + n) = make_float2(D[t][0] + bias0 + xv0.x,
                                         D[t][1] + bias0 + xv0.y);
        const float2 xv1 = *(const float2*)(xr1 + n);
        *(float2*)(o1 + n) = make_float2(D[t][2] + bias1 + xv1.x,
                                         D[t][3] + bias1 + xv1.y);
    }
}

// ============================================================
extern "C" void kernel_launch(void* const* d_in, const int* in_sizes, int n_in,
                              void* d_out, int out_size)
{
    const float* x    = (const float*)d_in[0];
    const float* g_w  = (const float*)d_in[1];
    const float* g_b  = (const float*)d_in[2];
    const float* th_w = (const float*)d_in[3];
    const float* th_b = (const float*)d_in[4];
    const float* ph_w = (const float*)d_in[5];
    const float* ph_b = (const float*)d_in[6];
    const float* W_w  = (const float*)d_in[7];
    const float* W_b  = (const float*)d_in[8];
    float* out = (float*)d_out;

    cudaFuncSetAttribute(proj_kernel,
                         cudaFuncAttributeMaxDynamicSharedMemorySize, PROJ_SMEM);
    cudaFuncSetAttribute(attn_kernel,
                         cudaFuncAttributeMaxDynamicSharedMemorySize, ATTN_SMEM);
    cudaFuncSetAttribute(out_kernel,
                         cudaFuncAttributeMaxDynamicSharedMemorySize, OUT_SMEM);

    dim3 g1(NSP / 128, BATCH);
    proj_kernel<<<g1, 256, PROJ_SMEM>>>(x, th_w, th_b, ph_w, ph_b, g_w, g_b);

    pool_kernel<<<BATCH * MSP, 128>>>();

    dim3 g2(NSP / 128, BATCH);
    attn_kernel<<<g2, 256, ATTN_SMEM>>>();

    dim3 g3(NSP / 128, CIN / 128, BATCH);
    out_kernel<<<g3, 256, OUT_SMEM>>>(x, W_w, W_b, out);
}

// round 7
// speedup vs baseline: 3.4362x; 1.0519x over previous
#include <cuda_runtime.h>
#include <cuda_bf16.h>
#include <cstdint>
#include <math.h>

#define BATCH 8
#define CIN   256
#define CI    128
#define NSP   6272   // 8*28*28
#define MSP   1568   // 8*14*14

// ---- scratch (static device arrays; allocation-free) ----
__device__ float g_Tphi[BATCH * NSP * CI];
__device__ float g_Tg  [BATCH * NSP * CI];
__device__ __nv_bfloat16 g_Qh[BATCH * NSP * CI];
__device__ __nv_bfloat16 g_Ql[BATCH * NSP * CI];
__device__ __nv_bfloat16 g_Kh[BATCH * MSP * CI];
__device__ __nv_bfloat16 g_Kl[BATCH * MSP * CI];
__device__ __nv_bfloat16 g_Vh[BATCH * MSP * CI];
__device__ __nv_bfloat16 g_Vl[BATCH * MSP * CI];
__device__ __nv_bfloat16 g_Yh[BATCH * NSP * CI];
__device__ __nv_bfloat16 g_Yl[BATCH * NSP * CI];
// pre-split weights
__device__ __nv_bfloat16 g_PWh[3 * 128 * 256];
__device__ __nv_bfloat16 g_PWl[3 * 128 * 256];
__device__ __nv_bfloat16 g_OWh[256 * 128];
__device__ __nv_bfloat16 g_OWl[256 * 128];

__device__ __forceinline__ uint32_t smem_u32(const void* p) {
    uint32_t a;
    asm("{ .reg .u64 t; cvta.to.shared.u64 t, %1; cvt.u32.u64 %0, t; }"
        : "=r"(a) : "l"(p));
    return a;
}

// ---- mma.sync / ldmatrix / cp.async (all sm_80 baseline ISA) ----
__device__ __forceinline__ void ldsm4(uint32_t (&r)[4], uint32_t addr) {
    asm volatile("ldmatrix.sync.aligned.m8n8.x4.shared.b16 {%0,%1,%2,%3}, [%4];"
        : "=r"(r[0]), "=r"(r[1]), "=r"(r[2]), "=r"(r[3]) : "r"(addr));
}
__device__ __forceinline__ void ldsm4t(uint32_t (&r)[4], uint32_t addr) {
    asm volatile("ldmatrix.sync.aligned.m8n8.x4.trans.shared.b16 {%0,%1,%2,%3}, [%4];"
        : "=r"(r[0]), "=r"(r[1]), "=r"(r[2]), "=r"(r[3]) : "r"(addr));
}
__device__ __forceinline__ void mma16816(float (&d)[4], const uint32_t (&a)[4],
                                         uint32_t b0, uint32_t b1) {
    asm volatile("mma.sync.aligned.m16n8k16.row.col.f32.bf16.bf16.f32 "
        "{%0,%1,%2,%3}, {%4,%5,%6,%7}, {%8,%9}, {%0,%1,%2,%3};"
        : "+f"(d[0]), "+f"(d[1]), "+f"(d[2]), "+f"(d[3])
        : "r"(a[0]), "r"(a[1]), "r"(a[2]), "r"(a[3]), "r"(b0), "r"(b1));
}
#define CP_ASYNC16(smem, gptr) \
    asm volatile("cp.async.cg.shared.global [%0], [%1], 16;" \
                 :: "r"(smem), "l"(gptr) : "memory")
#define CP_COMMIT() asm volatile("cp.async.commit_group;" ::: "memory")
#define CP_WAIT0()  asm volatile("cp.async.wait_group 0;" ::: "memory")
#define CP_WAIT1()  asm volatile("cp.async.wait_group 1;" ::: "memory")

// ============================================================
// Kernel 0: pre-split weights to bf16 hi/lo
// ============================================================
__global__ void prep_kernel(const float* __restrict__ th_w,
                            const float* __restrict__ ph_w,
                            const float* __restrict__ gw,
                            const float* __restrict__ Ww)
{
    const int i = blockIdx.x * blockDim.x + threadIdx.x;   // 0..131071
    const int PN = 128 * 256;
    float v; __nv_bfloat16 *dh, *dl;
    if (i < 3 * PN) {
        const int p = i / PN, o = i % PN;
        const float* s = (p == 0) ? th_w : (p == 1) ? ph_w : gw;
        v = s[o]; dh = g_PWh + i; dl = g_PWl + i;
    } else {
        const int o = i - 3 * PN;
        v = Ww[o]; dh = g_OWh + o; dl = g_OWl + o;
    }
    __nv_bfloat16 h = __float2bfloat16(v);
    *dh = h;
    *dl = __float2bfloat16(v - __bfloat162float(h));
}

// ============================================================
// Kernel 1: fused projections, split-bf16 mma.sync, cp.async double-buffered W.
// grid (49, 8), 256 threads. SMEM: Xh/Xl (139264) + 2 W buffers (2x36864).
// ============================================================
#define PX 136
#define PW 72
#define PS 136
#define PF 132
#define OFF_XL 69632
#define OFF_U  139264
#define WBUF   36864
#define W_LO   18432
#define PROJ_SMEM (139264 + 2 * 36864)   // 212992

__device__ __forceinline__ void proj_issueW(uint32_t sb,
        const __nv_bfloat16* __restrict__ wh,
        const __nv_bfloat16* __restrict__ wl,
        int chunk, int bufoff, int tid)
{
    const int cbase = chunk * 64;
    for (int i = tid; i < 1024; i += 256) {
        const int j = i >> 3, s = i & 7;
        const uint32_t d = sb + OFF_U + bufoff + j * 144 + s * 16;
        CP_ASYNC16(d,        wh + (size_t)j * CIN + cbase + s * 8);
        CP_ASYNC16(d + W_LO, wl + (size_t)j * CIN + cbase + s * 8);
    }
    CP_COMMIT();
}

__global__ __launch_bounds__(256) void proj_kernel(
    const float* __restrict__ x,
    const float* __restrict__ th_b, const float* __restrict__ ph_b,
    const float* __restrict__ gb)
{
    extern __shared__ __align__(16) char ps[];
    const int tid = threadIdx.x, lane = tid & 31, warp = tid >> 5;
    const int nb = blockIdx.x * 128, b = blockIdx.y;
    const uint32_t sb = smem_u32(ps);

    // prefetch p=0 chunk 0 while we split X
    proj_issueW(sb, g_PWh, g_PWl, 0, 0, tid);

    // ---- load + split X tile (256 c-rows x 128 n-cols) ----
    const float* xb = x + (size_t)b * CIN * NSP + nb;
    for (int i = tid; i < 256 * 32; i += 256) {
        const int c = i >> 5, n4 = (i & 31) << 2;
        float4 v = *(const float4*)(xb + (size_t)c * NSP + n4);
        __nv_bfloat162 h01 = __floats2bfloat162_rn(v.x, v.y);
        __nv_bfloat162 h23 = __floats2bfloat162_rn(v.z, v.w);
        *(__nv_bfloat162*)(ps + (c * PX + n4) * 2)     = h01;
        *(__nv_bfloat162*)(ps + (c * PX + n4) * 2 + 4) = h23;
        __nv_bfloat162 l01 = __floats2bfloat162_rn(v.x - __bfloat162float(h01.x),
                                                   v.y - __bfloat162float(h01.y));
        __nv_bfloat162 l23 = __floats2bfloat162_rn(v.z - __bfloat162float(h23.x),
                                                   v.w - __bfloat162float(h23.y));
        *(__nv_bfloat162*)(ps + OFF_XL + (c * PX + n4) * 2)     = l01;
        *(__nv_bfloat162*)(ps + OFF_XL + (c * PX + n4) * 2 + 4) = l23;
    }

    const uint32_t xRow = (lane & 7) + (((lane >> 3) & 1) << 3);
    const uint32_t aX = sb + (xRow * PX + ((lane >> 4) << 3)) * 2;
    const int j0 = warp * 16 + (lane >> 2), j1 = j0 + 8;

    for (int p = 0; p < 3; p++) {
        const __nv_bfloat16* wh = g_PWh + p * 32768;
        const __nv_bfloat16* wl = g_PWl + p * 32768;
        const float* bp = (p == 0) ? th_b : (p == 1) ? ph_b : gb;
        if (p > 0) proj_issueW(sb, wh, wl, 0, 0, tid);

        float D[16][4];
#pragma unroll
        for (int t = 0; t < 16; t++)
#pragma unroll
            for (int j = 0; j < 4; j++) D[t][j] = 0.f;

        for (int c = 0; c < 4; c++) {
            if (c < 3) proj_issueW(sb, wh, wl, c + 1, ((c + 1) & 1) * WBUF, tid);
            if (c < 3) { CP_WAIT1(); } else { CP_WAIT0(); }
            __syncthreads();
            const uint32_t aW = sb + OFF_U + (c & 1) * WBUF
                + ((warp * 16 + (lane & 15)) * PW + ((lane >> 4) << 3)) * 2;
#pragma unroll
            for (int kk2 = 0; kk2 < 4; kk2++) {
                uint32_t Ah[4], Al[4];
                ldsm4(Ah, aW + kk2 * 32);
                ldsm4(Al, aW + W_LO + kk2 * 32);
                const uint32_t xoff = (c * 4 + kk2) * (16 * PX * 2);
#pragma unroll
                for (int g = 0; g < 8; g++) {
                    uint32_t Bh[4], Bl[4];
                    ldsm4t(Bh, aX + xoff + g * 32);
                    ldsm4t(Bl, aX + OFF_XL + xoff + g * 32);
                    mma16816(D[2 * g],     Ah, Bh[0], Bh[1]);
                    mma16816(D[2 * g + 1], Ah, Bh[2], Bh[3]);
                    mma16816(D[2 * g],     Ah, Bl[0], Bl[1]);
                    mma16816(D[2 * g + 1], Ah, Bl[2], Bl[3]);
                    mma16816(D[2 * g],     Al, Bh[0], Bh[1]);
                    mma16816(D[2 * g + 1], Al, Bh[2], Bh[3]);
                }
            }
            __syncthreads();
        }

        const float bias0 = bp[j0], bias1 = bp[j1];
        if (p == 0) {
            // theta: split bf16 via staged transpose, two passes
            __nv_bfloat16* dsth = g_Qh + ((size_t)b * NSP + nb) * CI;
            __nv_bfloat16* dstl = g_Ql + ((size_t)b * NSP + nb) * CI;
#pragma unroll
            for (int t = 0; t < 16; t++) {
                const int n = t * 8 + (lane & 3) * 2;
                *(__nv_bfloat16*)(ps + OFF_U + (n * PS + j0) * 2)       = __float2bfloat16(D[t][0] + bias0);
                *(__nv_bfloat16*)(ps + OFF_U + ((n + 1) * PS + j0) * 2) = __float2bfloat16(D[t][1] + bias0);
                *(__nv_bfloat16*)(ps + OFF_U + (n * PS + j1) * 2)       = __float2bfloat16(D[t][2] + bias1);
                *(__nv_bfloat16*)(ps + OFF_U + ((n + 1) * PS + j1) * 2) = __float2bfloat16(D[t][3] + bias1);
            }
            __syncthreads();
            for (int i = tid; i < 128 * 16; i += 256) {
                const int n = i >> 4, j8 = (i & 15) << 3;
                *(uint4*)(dsth + (size_t)n * CI + j8) =
                    *(const uint4*)(ps + OFF_U + (n * PS + j8) * 2);
            }
            __syncthreads();
#pragma unroll
            for (int t = 0; t < 16; t++) {
                const int n = t * 8 + (lane & 3) * 2;
                const float v0 = D[t][0] + bias0, v1 = D[t][1] + bias0;
                const float v2 = D[t][2] + bias1, v3 = D[t][3] + bias1;
                *(__nv_bfloat16*)(ps + OFF_U + (n * PS + j0) * 2) =
                    __float2bfloat16(v0 - __bfloat162float(__float2bfloat16(v0)));
                *(__nv_bfloat16*)(ps + OFF_U + ((n + 1) * PS + j0) * 2) =
                    __float2bfloat16(v1 - __bfloat162float(__float2bfloat16(v1)));
                *(__nv_bfloat16*)(ps + OFF_U + (n * PS + j1) * 2) =
                    __float2bfloat16(v2 - __bfloat162float(__float2bfloat16(v2)));
                *(__nv_bfloat16*)(ps + OFF_U + ((n + 1) * PS + j1) * 2) =
                    __float2bfloat16(v3 - __bfloat162float(__float2bfloat16(v3)));
            }
            __syncthreads();
            for (int i = tid; i < 128 * 16; i += 256) {
                const int n = i >> 4, j8 = (i & 15) << 3;
                *(uint4*)(dstl + (size_t)n * CI + j8) =
                    *(const uint4*)(ps + OFF_U + (n * PS + j8) * 2);
            }
        } else {
            float* dst = ((p == 1) ? g_Tphi : g_Tg) + ((size_t)b * NSP + nb) * CI;
#pragma unroll
            for (int t = 0; t < 16; t++) {
                const int n = t * 8 + (lane & 3) * 2;
                *(float*)(ps + OFF_U + (n * PF + j0) * 4)       = D[t][0] + bias0;
                *(float*)(ps + OFF_U + ((n + 1) * PF + j0) * 4) = D[t][1] + bias0;
                *(float*)(ps + OFF_U + (n * PF + j1) * 4)       = D[t][2] + bias1;
                *(float*)(ps + OFF_U + ((n + 1) * PF + j1) * 4) = D[t][3] + bias1;
            }
            __syncthreads();
            for (int i = tid; i < 128 * 32; i += 256) {
                const int n = i >> 5, j4 = (i & 31) << 2;
                *(float4*)(dst + (size_t)n * CI + j4) =
                    *(const float4*)(ps + OFF_U + (n * PF + j4) * 4);
            }
        }
        __syncthreads();   // staging free before next projection's prefetch
    }
}

// ============================================================
// Kernel 2: 2x2 maxpool of phi/g -> bf16 hi/lo K and V, both (m, ci)
// ============================================================
__global__ void pool_kernel()
{
    const int bm = blockIdx.x;
    const int b = bm / MSP, m = bm % MSP;
    const int t = m / 196, rem = m % 196;
    const int h2 = rem / 14, w2 = rem % 14;
    const int n0 = t * 784 + (2 * h2) * 28 + 2 * w2;
    const int ci = threadIdx.x;
    const size_t base = (size_t)b * NSP * CI;
    const size_t o = ((size_t)b * MSP + m) * CI + ci;

    const float* p = g_Tphi;
    float pv = fmaxf(fmaxf(p[base + (size_t)n0 * CI + ci],
                           p[base + (size_t)(n0 + 1) * CI + ci]),
                     fmaxf(p[base + (size_t)(n0 + 28) * CI + ci],
                           p[base + (size_t)(n0 + 29) * CI + ci]));
    {
        __nv_bfloat16 h = __float2bfloat16(pv);
        g_Kh[o] = h;
        g_Kl[o] = __float2bfloat16(pv - __bfloat162float(h));
    }

    const float* gg = g_Tg;
    float gv = fmaxf(fmaxf(gg[base + (size_t)n0 * CI + ci],
                           gg[base + (size_t)(n0 + 1) * CI + ci]),
                     fmaxf(gg[base + (size_t)(n0 + 28) * CI + ci],
                           gg[base + (size_t)(n0 + 29) * CI + ci]));
    {
        __nv_bfloat16 h = __float2bfloat16(gv);
        g_Vh[o] = h;
        g_Vl[o] = __float2bfloat16(gv - __bfloat162float(h));
    }
}

// ============================================================
// Kernel 3: mma.sync flash attention, cp.async double-buffered 64-row KV chunks.
// grid (49, 8), 256 threads. SMEM: Qh/Ql (69632) + 2 KV buffers (2x69632).
// ============================================================
#define PQ 136
#define QTILE 34816          // 128*136*2
#define KTILE 17408          // 64*136*2
#define ABUF  69632
#define ABUFSZ 69632
#define ATTN_SMEM (69632 + 2 * 69632)   // 208896
#define NCH 25               // ceil(1568/64)

__global__ __launch_bounds__(256) void attn_kernel()
{
    extern __shared__ __align__(16) char smem[];
    const int tid = threadIdx.x, lane = tid & 31, warp = tid >> 5;
    const int qb = blockIdx.x * 128, b = blockIdx.y;
    const uint32_t sb = smem_u32(smem);

    const __nv_bfloat16* bKh = g_Kh + (size_t)b * MSP * CI;
    const __nv_bfloat16* bKl = g_Kl + (size_t)b * MSP * CI;
    const __nv_bfloat16* bVh = g_Vh + (size_t)b * MSP * CI;
    const __nv_bfloat16* bVl = g_Vl + (size_t)b * MSP * CI;

    // ---- issue chunk 0 (full rows: 16 x 16B segments per 128-bf16 row) ----
    {
        const uint32_t bo = sb + ABUF;
        for (int i = tid; i < 4096; i += 256) {
            const int t = i >> 10, r = (i >> 4) & 63, s = i & 15;
            const __nv_bfloat16* src =
                ((t == 0) ? bKh : (t == 1) ? bKl : (t == 2) ? bVh : bVl)
                + (size_t)r * CI + s * 8;
            CP_ASYNC16(bo + t * KTILE + r * 272 + s * 16, src);
        }
        CP_COMMIT();
    }

    // ---- load Q tiles (persistent) ----
    {
        const __nv_bfloat16* gqh = g_Qh + ((size_t)b * NSP + qb) * CI;
        const __nv_bfloat16* gql = g_Ql + ((size_t)b * NSP + qb) * CI;
        for (int i = tid; i < 128 * 16; i += 256) {
            const int r = i >> 4, c8 = (i & 15) << 3;
            *(uint4*)(smem + (r * PQ + c8) * 2) =
                *(const uint4*)(gqh + (size_t)r * CI + c8);
            *(uint4*)(smem + QTILE + (r * PQ + c8) * 2) =
                *(const uint4*)(gql + (size_t)r * CI + c8);
        }
    }

    const uint32_t aQH = sb + ((warp * 16 + (lane & 15)) * PQ + ((lane >> 4) << 3)) * 2;
    const uint32_t aQL = aQH + QTILE;
    const uint32_t kRow = (lane & 7) + ((lane >> 4) << 3);
    const uint32_t kOffB = (kRow * PQ + (((lane >> 3) & 1) << 3)) * 2;
    const uint32_t vRow = (lane & 7) + (((lane >> 3) & 1) << 3);
    const uint32_t vOffB = (vRow * PQ + ((lane >> 4) << 3)) * 2;

    float O[16][4];
#pragma unroll
    for (int t = 0; t < 16; t++)
#pragma unroll
        for (int j = 0; j < 4; j++) O[t][j] = 0.f;
    float m0 = -1e30f, m1 = -1e30f, l0 = 0.f, l1 = 0.f;

    for (int kt = 0; kt < NCH; kt++) {
        const int kvn = (MSP - kt * 64) < 64 ? (MSP - kt * 64) : 64;

        if (kt + 1 < NCH) {
            const int kvb1 = (kt + 1) * 64;
            const int kvn1 = (MSP - kvb1) < 64 ? (MSP - kvb1) : 64;
            const uint32_t bo = sb + ABUF + ((kt + 1) & 1) * ABUFSZ;
            for (int i = tid; i < 4096; i += 256) {
                const int t = i >> 10, r = (i >> 4) & 63, s = i & 15;
                if (r < kvn1) {
                    const __nv_bfloat16* src =
                        ((t == 0) ? bKh : (t == 1) ? bKl : (t == 2) ? bVh : bVl)
                        + (size_t)(kvb1 + r) * CI + s * 8;
                    CP_ASYNC16(bo + t * KTILE + r * 272 + s * 16, src);
                }
            }
            CP_COMMIT();
            CP_WAIT1();
        } else {
            CP_WAIT0();
        }
        __syncthreads();

        const uint32_t bo = sb + ABUF + (kt & 1) * ABUFSZ;
        const uint32_t aKH = bo + kOffB, aKL = aKH + KTILE;
        const uint32_t aVH = bo + 2 * KTILE + vOffB, aVL = aVH + KTILE;

        // ---- S = Qh Kh^T + Qh Kl^T + Ql Kh^T  (64 cols) ----
        float S[8][4];
#pragma unroll
        for (int t = 0; t < 8; t++)
#pragma unroll
            for (int j = 0; j < 4; j++) S[t][j] = 0.f;

#pragma unroll
        for (int kk = 0; kk < 8; kk++) {
            uint32_t Ah[4], Al[4];
            ldsm4(Ah, aQH + kk * 32);
            ldsm4(Al, aQL + kk * 32);
#pragma unroll
            for (int g = 0; g < 4; g++) {
                uint32_t Bh[4], Bl[4];
                ldsm4(Bh, aKH + g * (16 * PQ * 2) + kk * 32);
                ldsm4(Bl, aKL + g * (16 * PQ * 2) + kk * 32);
                mma16816(S[2 * g],     Ah, Bh[0], Bh[1]);
                mma16816(S[2 * g + 1], Ah, Bh[2], Bh[3]);
                mma16816(S[2 * g],     Ah, Bl[0], Bl[1]);
                mma16816(S[2 * g + 1], Ah, Bl[2], Bl[3]);
                mma16816(S[2 * g],     Al, Bh[0], Bh[1]);
                mma16816(S[2 * g + 1], Al, Bh[2], Bh[3]);
            }
        }

        if (kvn < 64) {
#pragma unroll
            for (int t = 0; t < 8; t++) {
                const int c0 = t * 8 + (lane & 3) * 2;
                if (c0 >= kvn)     { S[t][0] = -1e30f; S[t][2] = -1e30f; }
                if (c0 + 1 >= kvn) { S[t][1] = -1e30f; S[t][3] = -1e30f; }
            }
        }

        // ---- online softmax ----
        float mx0 = -1e30f, mx1 = -1e30f;
#pragma unroll
        for (int t = 0; t < 8; t++) {
            mx0 = fmaxf(mx0, fmaxf(S[t][0], S[t][1]));
            mx1 = fmaxf(mx1, fmaxf(S[t][2], S[t][3]));
        }
        mx0 = fmaxf(mx0, __shfl_xor_sync(0xffffffffu, mx0, 1));
        mx0 = fmaxf(mx0, __shfl_xor_sync(0xffffffffu, mx0, 2));
        mx1 = fmaxf(mx1, __shfl_xor_sync(0xffffffffu, mx1, 1));
        mx1 = fmaxf(mx1, __shfl_xor_sync(0xffffffffu, mx1, 2));
        const float mn0 = fmaxf(m0, mx0), mn1 = fmaxf(m1, mx1);
        const float f0 = __expf(m0 - mn0), f1 = __expf(m1 - mn1);
        m0 = mn0; m1 = mn1;
        float s0 = 0.f, s1 = 0.f;
#pragma unroll
        for (int t = 0; t < 8; t++) {
            S[t][0] = __expf(S[t][0] - mn0); s0 += S[t][0];
            S[t][1] = __expf(S[t][1] - mn0); s0 += S[t][1];
            S[t][2] = __expf(S[t][2] - mn1); s1 += S[t][2];
            S[t][3] = __expf(S[t][3] - mn1); s1 += S[t][3];
        }
        s0 += __shfl_xor_sync(0xffffffffu, s0, 1);
        s0 += __shfl_xor_sync(0xffffffffu, s0, 2);
        s1 += __shfl_xor_sync(0xffffffffu, s1, 1);
        s1 += __shfl_xor_sync(0xffffffffu, s1, 2);
        l0 = l0 * f0 + s0;
        l1 = l1 * f1 + s1;
#pragma unroll
        for (int t = 0; t < 16; t++) {
            O[t][0] *= f0; O[t][1] *= f0; O[t][2] *= f1; O[t][3] *= f1;
        }

        // ---- P -> bf16 hi/lo A-fragments (4 k16 steps) ----
        uint32_t Ph[4][4], Pl[4][4];
#pragma unroll
        for (int kk = 0; kk < 4; kk++) {
            const int t0 = 2 * kk, t1 = 2 * kk + 1;
#pragma unroll
            for (int q = 0; q < 4; q++) {
                const int tt = (q < 2) ? t0 : t1;
                const int jj = (q & 1) * 2;
                const float p0 = S[tt][jj], p1 = S[tt][jj + 1];
                __nv_bfloat162 h2 = __floats2bfloat162_rn(p0, p1);
                Ph[kk][q] = *(uint32_t*)&h2;
                __nv_bfloat162 l2 = __floats2bfloat162_rn(
                    p0 - __bfloat162float(h2.x), p1 - __bfloat162float(h2.y));
                Pl[kk][q] = *(uint32_t*)&l2;
            }
        }

        // ---- O += Ph Vh + Ph Vl + Pl Vh ----
#pragma unroll
        for (int kk = 0; kk < 4; kk++) {
#pragma unroll
            for (int g = 0; g < 8; g++) {
                uint32_t Vh4[4], Vl4[4];
                ldsm4t(Vh4, aVH + kk * (16 * PQ * 2) + g * 32);
                ldsm4t(Vl4, aVL + kk * (16 * PQ * 2) + g * 32);
                mma16816(O[2 * g],     Ph[kk], Vh4[0], Vh4[1]);
                mma16816(O[2 * g + 1], Ph[kk], Vh4[2], Vh4[3]);
                mma16816(O[2 * g],     Ph[kk], Vl4[0], Vl4[1]);
                mma16816(O[2 * g + 1], Ph[kk], Vl4[2], Vl4[3]);
                mma16816(O[2 * g],     Pl[kk], Vh4[0], Vh4[1]);
                mma16816(O[2 * g + 1], Pl[kk], Vh4[2], Vh4[3]);
            }
        }
        __syncthreads();
    }

    // ---- y = O / l, pre-split bf16 hi/lo ----
    {
        const float inv0 = 1.0f / l0, inv1 = 1.0f / l1;
        const int r0 = qb + warp * 16 + (lane >> 2);
        const size_t base0 = ((size_t)b * NSP + r0) * CI + (lane & 3) * 2;
        const size_t base1 = base0 + 8 * CI;
#pragma unroll
        for (int t = 0; t < 16; t++) {
            const float v0 = O[t][0] * inv0, v1 = O[t][1] * inv0;
            __nv_bfloat162 h = __floats2bfloat162_rn(v0, v1);
            *(__nv_bfloat162*)(g_Yh + base0 + t * 8) = h;
            *(__nv_bfloat162*)(g_Yl + base0 + t * 8) = __floats2bfloat162_rn(
                v0 - __bfloat162float(h.x), v1 - __bfloat162float(h.y));
            const float w0 = O[t][2] * inv1, w1 = O[t][3] * inv1;
            __nv_bfloat162 h2 = __floats2bfloat162_rn(w0, w1);
            *(__nv_bfloat162*)(g_Yh + base1 + t * 8) = h2;
            *(__nv_bfloat162*)(g_Yl + base1 + t * 8) = __floats2bfloat162_rn(
                w0 - __bfloat162float(h2.x), w1 - __bfloat162float(h2.y));
        }
    }
}

// ============================================================
// Kernel 4: out = W*y + b + x, co=128 x n=64 tiles, 2 CTAs/SM, cp.async.
// grid (98, 2, 8), 256 threads.
// ============================================================
#define OW_WL 34816
#define OW_YH 69632
#define OW_YL 87040
#define OUT_SMEM 104448

__global__ __launch_bounds__(256) void out_kernel(
    const float* __restrict__ x, const float* __restrict__ Wb,
    float* __restrict__ out)
{
    extern __shared__ __align__(16) char ps[];
    const int tid = threadIdx.x, lane = tid & 31, warp = tid >> 5;
    const int nb = blockIdx.x * 64, co0 = blockIdx.y * 128, b = blockIdx.z;
    const uint32_t sb = smem_u32(ps);

    // cp.async W (pre-split) and Y tiles
    for (int i = tid; i < 2048; i += 256) {
        const int co = i >> 4, s = i & 15;
        const size_t gsrc = (size_t)(co0 + co) * CI + s * 8;
        CP_ASYNC16(sb + co * 272 + s * 16,         g_OWh + gsrc);
        CP_ASYNC16(sb + OW_WL + co * 272 + s * 16, g_OWl + gsrc);
    }
    {
        const __nv_bfloat16* yh = g_Yh + ((size_t)b * NSP + nb) * CI;
        const __nv_bfloat16* yl = g_Yl + ((size_t)b * NSP + nb) * CI;
        for (int i = tid; i < 1024; i += 256) {
            const int n = i >> 4, s = i & 15;
            const size_t gsrc = (size_t)n * CI + s * 8;
            CP_ASYNC16(sb + OW_YH + n * 272 + s * 16, yh + gsrc);
            CP_ASYNC16(sb + OW_YL + n * 272 + s * 16, yl + gsrc);
        }
    }
    CP_COMMIT();
    CP_WAIT0();
    __syncthreads();

    float D[8][4];
#pragma unroll
    for (int t = 0; t < 8; t++)
#pragma unroll
        for (int j = 0; j < 4; j++) D[t][j] = 0.f;

    const uint32_t aW = sb + ((warp * 16 + (lane & 15)) * 136 + ((lane >> 4) << 3)) * 2;
    const uint32_t kRow = (lane & 7) + ((lane >> 4) << 3);
    const uint32_t aY = sb + OW_YH + (kRow * 136 + (((lane >> 3) & 1) << 3)) * 2;

#pragma unroll
    for (int kk = 0; kk < 8; kk++) {
        uint32_t Ah[4], Al[4];
        ldsm4(Ah, aW + kk * 32);
        ldsm4(Al, aW + OW_WL + kk * 32);
#pragma unroll
        for (int g = 0; g < 4; g++) {
            uint32_t Bh[4], Bl[4];
            ldsm4(Bh, aY + g * (16 * 136 * 2) + kk * 32);
            ldsm4(Bl, aY + (OW_YL - OW_YH) + g * (16 * 136 * 2) + kk * 32);
            mma16816(D[2 * g],     Ah, Bh[0], Bh[1]);
            mma16816(D[2 * g + 1], Ah, Bh[2], Bh[3]);
            mma16816(D[2 * g],     Ah, Bl[0], Bl[1]);
            mma16816(D[2 * g + 1], Ah, Bl[2], Bl[3]);
            mma16816(D[2 * g],     Al, Bh[0], Bh[1]);
            mma16816(D[2 * g + 1], Al, Bh[2], Bh[3]);
        }
    }

    const int co = co0 + warp * 16 + (lane >> 2);
    const float bias0 = Wb[co], bias1 = Wb[co + 8];
    const float* xr0 = x + ((size_t)b * CIN + co) * NSP + nb;
    const float* xr1 = xr0 + (size_t)8 * NSP;
    float* o0 = out + ((size_t)b * CIN + co) * NSP + nb;
    float* o1 = o0 + (size_t)8 * NSP;
#pragma unroll
    for (int t = 0; t < 8; t++) {
        const int n = t * 8 + (lane & 3) * 2;
        const float2 xv0 = *(const float2*)(xr0 + n);
        *(float2*)(o0 + n) = make_float2(D[t][0] + bias0 + xv0.x,
                                         D[t][1] + bias0 + xv0.y);
        const float2 xv1 = *(const float2*)(xr1 + n);
        *(float2*)(o1 + n) = make_float2(D[t][2] + bias1 + xv1.x,
                                         D[t][3] + bias1 + xv1.y);
    }
}

// ============================================================
extern "C" void kernel_launch(void* const* d_in, const int* in_sizes, int n_in,
                              void* d_out, int out_size)
{
    const float* x    = (const float*)d_in[0];
    const float* g_w  = (const float*)d_in[1];
    const float* g_b  = (const float*)d_in[2];
    const float* th_w = (const float*)d_in[3];
    const float* th_b = (const float*)d_in[4];
    const float* ph_w = (const float*)d_in[5];
    const float* ph_b = (const float*)d_in[6];
    const float* W_w  = (const float*)d_in[7];
    const float* W_b  = (const float*)d_in[8];
    float* out = (float*)d_out;

    cudaFuncSetAttribute(proj_kernel,
                         cudaFuncAttributeMaxDynamicSharedMemorySize, PROJ_SMEM);
    cudaFuncSetAttribute(attn_kernel,
                         cudaFuncAttributeMaxDynamicSharedMemorySize, ATTN_SMEM);
    cudaFuncSetAttribute(out_kernel,
                         cudaFuncAttributeMaxDynamicSharedMemorySize, OUT_SMEM);

    prep_kernel<<<512, 256>>>(th_w, ph_w, g_w, W_w);

    dim3 g1(NSP / 128, BATCH);
    proj_kernel<<<g1, 256, PROJ_SMEM>>>(x, th_b, ph_b, g_b);

    pool_kernel<<<BATCH * MSP, 128>>>();

    dim3 g2(NSP / 128, BATCH);
    attn_kernel<<<g2, 256, ATTN_SMEM>>>();

    dim3 g3(NSP / 64, CIN / 128, BATCH);
    out_kernel<<<g3, 256, OUT_SMEM>>>(x, W_b, out);
}

// round 9
// speedup vs baseline: 3.5166x; 1.0234x over previous
#include <cuda_runtime.h>
#include <cuda_bf16.h>
#include <cstdint>
#include <math.h>

#define BATCH 8
#define CIN   256
#define CI    128
#define NSP   6272   // 8*28*28
#define MSP   1568   // 8*14*14

// ---- scratch (static device arrays; allocation-free) ----
__device__ float g_Tphi[BATCH * NSP * CI];
__device__ float g_Tg  [BATCH * NSP * CI];
__device__ __nv_bfloat16 g_Qh[BATCH * NSP * CI];
__device__ __nv_bfloat16 g_Ql[BATCH * NSP * CI];
__device__ __nv_bfloat16 g_Kh[BATCH * MSP * CI];
__device__ __nv_bfloat16 g_Kl[BATCH * MSP * CI];
__device__ __nv_bfloat16 g_Vh[BATCH * MSP * CI];
__device__ __nv_bfloat16 g_Vl[BATCH * MSP * CI];
__device__ __nv_bfloat16 g_Yh[BATCH * NSP * CI];
__device__ __nv_bfloat16 g_Yl[BATCH * NSP * CI];
// pre-split weights
__device__ __nv_bfloat16 g_PWh[3 * 128 * 256];
__device__ __nv_bfloat16 g_PWl[3 * 128 * 256];
__device__ __nv_bfloat16 g_OWh[256 * 128];
__device__ __nv_bfloat16 g_OWl[256 * 128];

__device__ __forceinline__ uint32_t smem_u32(const void* p) {
    uint32_t a;
    asm("{ .reg .u64 t; cvta.to.shared.u64 t, %1; cvt.u32.u64 %0, t; }"
        : "=r"(a) : "l"(p));
    return a;
}

// ---- mma.sync / ldmatrix / cp.async (all sm_80 baseline ISA) ----
__device__ __forceinline__ void ldsm4(uint32_t (&r)[4], uint32_t addr) {
    asm volatile("ldmatrix.sync.aligned.m8n8.x4.shared.b16 {%0,%1,%2,%3}, [%4];"
        : "=r"(r[0]), "=r"(r[1]), "=r"(r[2]), "=r"(r[3]) : "r"(addr));
}
__device__ __forceinline__ void ldsm4t(uint32_t (&r)[4], uint32_t addr) {
    asm volatile("ldmatrix.sync.aligned.m8n8.x4.trans.shared.b16 {%0,%1,%2,%3}, [%4];"
        : "=r"(r[0]), "=r"(r[1]), "=r"(r[2]), "=r"(r[3]) : "r"(addr));
}
__device__ __forceinline__ void mma16816(float (&d)[4], const uint32_t (&a)[4],
                                         uint32_t b0, uint32_t b1) {
    asm volatile("mma.sync.aligned.m16n8k16.row.col.f32.bf16.bf16.f32 "
        "{%0,%1,%2,%3}, {%4,%5,%6,%7}, {%8,%9}, {%0,%1,%2,%3};"
        : "+f"(d[0]), "+f"(d[1]), "+f"(d[2]), "+f"(d[3])
        : "r"(a[0]), "r"(a[1]), "r"(a[2]), "r"(a[3]), "r"(b0), "r"(b1));
}
#define CP_ASYNC16(smem, gptr) \
    asm volatile("cp.async.cg.shared.global [%0], [%1], 16;" \
                 :: "r"(smem), "l"(gptr) : "memory")
#define CP_COMMIT() asm volatile("cp.async.commit_group;" ::: "memory")
#define CP_WAIT0()  asm volatile("cp.async.wait_group 0;" ::: "memory")
#define CP_WAIT1()  asm volatile("cp.async.wait_group 1;" ::: "memory")

// ============================================================
// Kernel 0: pre-split weights to bf16 hi/lo
// ============================================================
__global__ void prep_kernel(const float* __restrict__ th_w,
                            const float* __restrict__ ph_w,
                            const float* __restrict__ gw,
                            const float* __restrict__ Ww)
{
    const int i = blockIdx.x * blockDim.x + threadIdx.x;   // 0..131071
    const int PN = 128 * 256;
    float v; __nv_bfloat16 *dh, *dl;
    if (i < 3 * PN) {
        const int p = i / PN, o = i % PN;
        const float* s = (p == 0) ? th_w : (p == 1) ? ph_w : gw;
        v = s[o]; dh = g_PWh + i; dl = g_PWl + i;
    } else {
        const int o = i - 3 * PN;
        v = Ww[o]; dh = g_OWh + o; dl = g_OWl + o;
    }
    __nv_bfloat16 h = __float2bfloat16(v);
    *dh = h;
    *dl = __float2bfloat16(v - __bfloat162float(h));
}

// ============================================================
// Kernel 1: fused projections, split-bf16 mma.sync, cp.async double-buffered W.
// grid (49, 8), 256 threads. SMEM: Xh/Xl (139264) + 2 W buffers (2x36864).
// ============================================================
#define PX 136
#define PW 72
#define PS 136
#define PF 132
#define OFF_XL 69632
#define OFF_U  139264
#define WBUF   36864
#define W_LO   18432
#define PROJ_SMEM (139264 + 2 * 36864)   // 212992

__device__ __forceinline__ void proj_issueW(uint32_t sb,
        const __nv_bfloat16* __restrict__ wh,
        const __nv_bfloat16* __restrict__ wl,
        int chunk, int bufoff, int tid)
{
    const int cbase = chunk * 64;
    for (int i = tid; i < 1024; i += 256) {
        const int j = i >> 3, s = i & 7;
        const uint32_t d = sb + OFF_U + bufoff + j * 144 + s * 16;
        CP_ASYNC16(d,        wh + (size_t)j * CIN + cbase + s * 8);
        CP_ASYNC16(d + W_LO, wl + (size_t)j * CIN + cbase + s * 8);
    }
    CP_COMMIT();
}

__global__ __launch_bounds__(256) void proj_kernel(
    const float* __restrict__ x,
    const float* __restrict__ th_b, const float* __restrict__ ph_b,
    const float* __restrict__ gb)
{
    extern __shared__ __align__(16) char ps[];
    const int tid = threadIdx.x, lane = tid & 31, warp = tid >> 5;
    const int nb = blockIdx.x * 128, b = blockIdx.y;
    const uint32_t sb = smem_u32(ps);

    // prefetch p=0 chunk 0 while we split X
    proj_issueW(sb, g_PWh, g_PWl, 0, 0, tid);

    // ---- load + split X tile (256 c-rows x 128 n-cols) ----
    const float* xb = x + (size_t)b * CIN * NSP + nb;
    for (int i = tid; i < 256 * 32; i += 256) {
        const int c = i >> 5, n4 = (i & 31) << 2;
        float4 v = *(const float4*)(xb + (size_t)c * NSP + n4);
        __nv_bfloat162 h01 = __floats2bfloat162_rn(v.x, v.y);
        __nv_bfloat162 h23 = __floats2bfloat162_rn(v.z, v.w);
        *(__nv_bfloat162*)(ps + (c * PX + n4) * 2)     = h01;
        *(__nv_bfloat162*)(ps + (c * PX + n4) * 2 + 4) = h23;
        __nv_bfloat162 l01 = __floats2bfloat162_rn(v.x - __bfloat162float(h01.x),
                                                   v.y - __bfloat162float(h01.y));
        __nv_bfloat162 l23 = __floats2bfloat162_rn(v.z - __bfloat162float(h23.x),
                                                   v.w - __bfloat162float(h23.y));
        *(__nv_bfloat162*)(ps + OFF_XL + (c * PX + n4) * 2)     = l01;
        *(__nv_bfloat162*)(ps + OFF_XL + (c * PX + n4) * 2 + 4) = l23;
    }

    const uint32_t xRow = (lane & 7) + (((lane >> 3) & 1) << 3);
    const uint32_t aX = sb + (xRow * PX + ((lane >> 4) << 3)) * 2;
    const int j0 = warp * 16 + (lane >> 2), j1 = j0 + 8;

    for (int p = 0; p < 3; p++) {
        const __nv_bfloat16* wh = g_PWh + p * 32768;
        const __nv_bfloat16* wl = g_PWl + p * 32768;
        const float* bp = (p == 0) ? th_b : (p == 1) ? ph_b : gb;
        if (p > 0) proj_issueW(sb, wh, wl, 0, 0, tid);

        float D[16][4];
#pragma unroll
        for (int t = 0; t < 16; t++)
#pragma unroll
            for (int j = 0; j < 4; j++) D[t][j] = 0.f;

        for (int c = 0; c < 4; c++) {
            if (c < 3) proj_issueW(sb, wh, wl, c + 1, ((c + 1) & 1) * WBUF, tid);
            if (c < 3) { CP_WAIT1(); } else { CP_WAIT0(); }
            __syncthreads();
            const uint32_t aW = sb + OFF_U + (c & 1) * WBUF
                + ((warp * 16 + (lane & 15)) * PW + ((lane >> 4) << 3)) * 2;
#pragma unroll
            for (int kk2 = 0; kk2 < 4; kk2++) {
                uint32_t Ah[4], Al[4];
                ldsm4(Ah, aW + kk2 * 32);
                ldsm4(Al, aW + W_LO + kk2 * 32);
                const uint32_t xoff = (c * 4 + kk2) * (16 * PX * 2);
#pragma unroll
                for (int g = 0; g < 8; g++) {
                    uint32_t Bh[4], Bl[4];
                    ldsm4t(Bh, aX + xoff + g * 32);
                    ldsm4t(Bl, aX + OFF_XL + xoff + g * 32);
                    mma16816(D[2 * g],     Ah, Bh[0], Bh[1]);
                    mma16816(D[2 * g + 1], Ah, Bh[2], Bh[3]);
                    mma16816(D[2 * g],     Ah, Bl[0], Bl[1]);
                    mma16816(D[2 * g + 1], Ah, Bl[2], Bl[3]);
                    mma16816(D[2 * g],     Al, Bh[0], Bh[1]);
                    mma16816(D[2 * g + 1], Al, Bh[2], Bh[3]);
                }
            }
            __syncthreads();
        }

        const float bias0 = bp[j0], bias1 = bp[j1];
        if (p == 0) {
            // theta: split bf16 via staged transpose, two passes
            __nv_bfloat16* dsth = g_Qh + ((size_t)b * NSP + nb) * CI;
            __nv_bfloat16* dstl = g_Ql + ((size_t)b * NSP + nb) * CI;
#pragma unroll
            for (int t = 0; t < 16; t++) {
                const int n = t * 8 + (lane & 3) * 2;
                *(__nv_bfloat16*)(ps + OFF_U + (n * PS + j0) * 2)       = __float2bfloat16(D[t][0] + bias0);
                *(__nv_bfloat16*)(ps + OFF_U + ((n + 1) * PS + j0) * 2) = __float2bfloat16(D[t][1] + bias0);
                *(__nv_bfloat16*)(ps + OFF_U + (n * PS + j1) * 2)       = __float2bfloat16(D[t][2] + bias1);
                *(__nv_bfloat16*)(ps + OFF_U + ((n + 1) * PS + j1) * 2) = __float2bfloat16(D[t][3] + bias1);
            }
            __syncthreads();
            for (int i = tid; i < 128 * 16; i += 256) {
                const int n = i >> 4, j8 = (i & 15) << 3;
                *(uint4*)(dsth + (size_t)n * CI + j8) =
                    *(const uint4*)(ps + OFF_U + (n * PS + j8) * 2);
            }
            __syncthreads();
#pragma unroll
            for (int t = 0; t < 16; t++) {
                const int n = t * 8 + (lane & 3) * 2;
                const float v0 = D[t][0] + bias0, v1 = D[t][1] + bias0;
                const float v2 = D[t][2] + bias1, v3 = D[t][3] + bias1;
                *(__nv_bfloat16*)(ps + OFF_U + (n * PS + j0) * 2) =
                    __float2bfloat16(v0 - __bfloat162float(__float2bfloat16(v0)));
                *(__nv_bfloat16*)(ps + OFF_U + ((n + 1) * PS + j0) * 2) =
                    __float2bfloat16(v1 - __bfloat162float(__float2bfloat16(v1)));
                *(__nv_bfloat16*)(ps + OFF_U + (n * PS + j1) * 2) =
                    __float2bfloat16(v2 - __bfloat162float(__float2bfloat16(v2)));
                *(__nv_bfloat16*)(ps + OFF_U + ((n + 1) * PS + j1) * 2) =
                    __float2bfloat16(v3 - __bfloat162float(__float2bfloat16(v3)));
            }
            __syncthreads();
            for (int i = tid; i < 128 * 16; i += 256) {
                const int n = i >> 4, j8 = (i & 15) << 3;
                *(uint4*)(dstl + (size_t)n * CI + j8) =
                    *(const uint4*)(ps + OFF_U + (n * PS + j8) * 2);
            }
        } else {
            float* dst = ((p == 1) ? g_Tphi : g_Tg) + ((size_t)b * NSP + nb) * CI;
#pragma unroll
            for (int t = 0; t < 16; t++) {
                const int n = t * 8 + (lane & 3) * 2;
                *(float*)(ps + OFF_U + (n * PF + j0) * 4)       = D[t][0] + bias0;
                *(float*)(ps + OFF_U + ((n + 1) * PF + j0) * 4) = D[t][1] + bias0;
                *(float*)(ps + OFF_U + (n * PF + j1) * 4)       = D[t][2] + bias1;
                *(float*)(ps + OFF_U + ((n + 1) * PF + j1) * 4) = D[t][3] + bias1;
            }
            __syncthreads();
            for (int i = tid; i < 128 * 32; i += 256) {
                const int n = i >> 5, j4 = (i & 31) << 2;
                *(float4*)(dst + (size_t)n * CI + j4) =
                    *(const float4*)(ps + OFF_U + (n * PF + j4) * 4);
            }
        }
        __syncthreads();   // staging free before next projection's prefetch
    }
}

// ============================================================
// Kernel 2: 2x2 maxpool of phi/g -> bf16 hi/lo K and V, both (m, ci)
// ============================================================
__global__ void pool_kernel()
{
    const int bm = blockIdx.x;
    const int b = bm / MSP, m = bm % MSP;
    const int t = m / 196, rem = m % 196;
    const int h2 = rem / 14, w2 = rem % 14;
    const int n0 = t * 784 + (2 * h2) * 28 + 2 * w2;
    const int ci = threadIdx.x;
    const size_t base = (size_t)b * NSP * CI;
    const size_t o = ((size_t)b * MSP + m) * CI + ci;

    const float* p = g_Tphi;
    float pv = fmaxf(fmaxf(p[base + (size_t)n0 * CI + ci],
                           p[base + (size_t)(n0 + 1) * CI + ci]),
                     fmaxf(p[base + (size_t)(n0 + 28) * CI + ci],
                           p[base + (size_t)(n0 + 29) * CI + ci]));
    {
        __nv_bfloat16 h = __float2bfloat16(pv);
        g_Kh[o] = h;
        g_Kl[o] = __float2bfloat16(pv - __bfloat162float(h));
    }

    const float* gg = g_Tg;
    float gv = fmaxf(fmaxf(gg[base + (size_t)n0 * CI + ci],
                           gg[base + (size_t)(n0 + 1) * CI + ci]),
                     fmaxf(gg[base + (size_t)(n0 + 28) * CI + ci],
                           gg[base + (size_t)(n0 + 29) * CI + ci]));
    {
        __nv_bfloat16 h = __float2bfloat16(gv);
        g_Vh[o] = h;
        g_Vl[o] = __float2bfloat16(gv - __bfloat162float(h));
    }
}

// ============================================================
// Kernel 3: mma.sync flash attention, 2 CTAs/SM for phase overlap.
// grid (98, 8), 128 threads (4 warps; warp owns 16 q-rows x full cols).
// Q tile 64 rows; KV chunks of 32, cp.async double-buffered; 49 exact chunks.
// SMEM: Qh/Ql (34816) + 2 KV buffers (2x34816) = 104448 -> 2 CTAs/SM.
// ============================================================
#define PQ 136
#define QT    17408          // 64*136*2
#define KT    8704           // 32*136*2
#define KVOFF 34816          // Q region size (Qh+Ql)
#define KVB   34816          // one KV buffer (Kh,Kl,Vh,Vl)
#define ATTN_SMEM (34816 + 2 * 34816)   // 104448
#define NCH 49               // 1568 / 32 exactly

__global__ __launch_bounds__(128, 2) void attn_kernel()
{
    extern __shared__ __align__(16) char smem[];
    const int tid = threadIdx.x, lane = tid & 31, warp = tid >> 5;
    const int qb = blockIdx.x * 64, b = blockIdx.y;
    const uint32_t sb = smem_u32(smem);

    const __nv_bfloat16* bKh = g_Kh + (size_t)b * MSP * CI;
    const __nv_bfloat16* bKl = g_Kl + (size_t)b * MSP * CI;
    const __nv_bfloat16* bVh = g_Vh + (size_t)b * MSP * CI;
    const __nv_bfloat16* bVl = g_Vl + (size_t)b * MSP * CI;

    // ---- issue chunk 0 (4 tiles x 32 rows x 16 segments) ----
    {
        const uint32_t bo = sb + KVOFF;
        for (int i = tid; i < 2048; i += 128) {
            const int t = i >> 9, r = (i >> 4) & 31, s = i & 15;
            const __nv_bfloat16* src =
                ((t == 0) ? bKh : (t == 1) ? bKl : (t == 2) ? bVh : bVl)
                + (size_t)r * CI + s * 8;
            CP_ASYNC16(bo + t * KT + r * 272 + s * 16, src);
        }
        CP_COMMIT();
    }

    // ---- load Q tiles (persistent, 64 rows) ----
    {
        const __nv_bfloat16* gqh = g_Qh + ((size_t)b * NSP + qb) * CI;
        const __nv_bfloat16* gql = g_Ql + ((size_t)b * NSP + qb) * CI;
        for (int i = tid; i < 64 * 16; i += 128) {
            const int r = i >> 4, c8 = (i & 15) << 3;
            *(uint4*)(smem + (r * PQ + c8) * 2) =
                *(const uint4*)(gqh + (size_t)r * CI + c8);
            *(uint4*)(smem + QT + (r * PQ + c8) * 2) =
                *(const uint4*)(gql + (size_t)r * CI + c8);
        }
    }

    const uint32_t aQH = sb + ((warp * 16 + (lane & 15)) * PQ + ((lane >> 4) << 3)) * 2;
    const uint32_t aQL = aQH + QT;
    const uint32_t kRow = (lane & 7) + ((lane >> 4) << 3);
    const uint32_t kOffB = (kRow * PQ + (((lane >> 3) & 1) << 3)) * 2;
    const uint32_t vRow = (lane & 7) + (((lane >> 3) & 1) << 3);
    const uint32_t vOffB = (vRow * PQ + ((lane >> 4) << 3)) * 2;

    float O[16][4];
#pragma unroll
    for (int t = 0; t < 16; t++)
#pragma unroll
        for (int j = 0; j < 4; j++) O[t][j] = 0.f;
    float m0 = -1e30f, m1 = -1e30f, l0 = 0.f, l1 = 0.f;

    for (int kt = 0; kt < NCH; kt++) {
        if (kt + 1 < NCH) {
            const int kvb1 = (kt + 1) * 32;
            const uint32_t bo = sb + KVOFF + ((kt + 1) & 1) * KVB;
            for (int i = tid; i < 2048; i += 128) {
                const int t = i >> 9, r = (i >> 4) & 31, s = i & 15;
                const __nv_bfloat16* src =
                    ((t == 0) ? bKh : (t == 1) ? bKl : (t == 2) ? bVh : bVl)
                    + (size_t)(kvb1 + r) * CI + s * 8;
                CP_ASYNC16(bo + t * KT + r * 272 + s * 16, src);
            }
            CP_COMMIT();
            CP_WAIT1();
        } else {
            CP_WAIT0();
        }
        __syncthreads();

        const uint32_t bo = sb + KVOFF + (kt & 1) * KVB;
        const uint32_t aKH = bo + kOffB, aKL = aKH + KT;
        const uint32_t aVH = bo + 2 * KT + vOffB, aVL = aVH + KT;

        // ---- S = Qh Kh^T + Qh Kl^T + Ql Kh^T  (32 cols) ----
        float S[4][4];
#pragma unroll
        for (int t = 0; t < 4; t++)
#pragma unroll
            for (int j = 0; j < 4; j++) S[t][j] = 0.f;

#pragma unroll
        for (int kk = 0; kk < 8; kk++) {
            uint32_t Ah[4], Al[4];
            ldsm4(Ah, aQH + kk * 32);
            ldsm4(Al, aQL + kk * 32);
#pragma unroll
            for (int g = 0; g < 2; g++) {
                uint32_t Bh[4], Bl[4];
                ldsm4(Bh, aKH + g * (16 * PQ * 2) + kk * 32);
                ldsm4(Bl, aKL + g * (16 * PQ * 2) + kk * 32);
                mma16816(S[2 * g],     Ah, Bh[0], Bh[1]);
                mma16816(S[2 * g + 1], Ah, Bh[2], Bh[3]);
                mma16816(S[2 * g],     Ah, Bl[0], Bl[1]);
                mma16816(S[2 * g + 1], Ah, Bl[2], Bl[3]);
                mma16816(S[2 * g],     Al, Bh[0], Bh[1]);
                mma16816(S[2 * g + 1], Al, Bh[2], Bh[3]);
            }
        }

        // ---- online softmax (1568 = 49*32 exactly; no tail mask) ----
        float mx0 = -1e30f, mx1 = -1e30f;
#pragma unroll
        for (int t = 0; t < 4; t++) {
            mx0 = fmaxf(mx0, fmaxf(S[t][0], S[t][1]));
            mx1 = fmaxf(mx1, fmaxf(S[t][2], S[t][3]));
        }
        mx0 = fmaxf(mx0, __shfl_xor_sync(0xffffffffu, mx0, 1));
        mx0 = fmaxf(mx0, __shfl_xor_sync(0xffffffffu, mx0, 2));
        mx1 = fmaxf(mx1, __shfl_xor_sync(0xffffffffu, mx1, 1));
        mx1 = fmaxf(mx1, __shfl_xor_sync(0xffffffffu, mx1, 2));
        const float mn0 = fmaxf(m0, mx0), mn1 = fmaxf(m1, mx1);
        const float f0 = __expf(m0 - mn0), f1 = __expf(m1 - mn1);
        m0 = mn0; m1 = mn1;
        float s0 = 0.f, s1 = 0.f;
#pragma unroll
        for (int t = 0; t < 4; t++) {
            S[t][0] = __expf(S[t][0] - mn0); s0 += S[t][0];
            S[t][1] = __expf(S[t][1] - mn0); s0 += S[t][1];
            S[t][2] = __expf(S[t][2] - mn1); s1 += S[t][2];
            S[t][3] = __expf(S[t][3] - mn1); s1 += S[t][3];
        }
        s0 += __shfl_xor_sync(0xffffffffu, s0, 1);
        s0 += __shfl_xor_sync(0xffffffffu, s0, 2);
        s1 += __shfl_xor_sync(0xffffffffu, s1, 1);
        s1 += __shfl_xor_sync(0xffffffffu, s1, 2);
        l0 = l0 * f0 + s0;
        l1 = l1 * f1 + s1;
#pragma unroll
        for (int t = 0; t < 16; t++) {
            O[t][0] *= f0; O[t][1] *= f0; O[t][2] *= f1; O[t][3] *= f1;
        }

        // ---- P -> bf16 hi/lo A-fragments (2 k16 steps) ----
        uint32_t Ph[2][4], Pl[2][4];
#pragma unroll
        for (int kk = 0; kk < 2; kk++) {
            const int t0 = 2 * kk, t1 = 2 * kk + 1;
#pragma unroll
            for (int q = 0; q < 4; q++) {
                const int tt = (q < 2) ? t0 : t1;
                const int jj = (q & 1) * 2;
                const float p0 = S[tt][jj], p1 = S[tt][jj + 1];
                __nv_bfloat162 h2 = __floats2bfloat162_rn(p0, p1);
                Ph[kk][q] = *(uint32_t*)&h2;
                __nv_bfloat162 l2 = __floats2bfloat162_rn(
                    p0 - __bfloat162float(h2.x), p1 - __bfloat162float(h2.y));
                Pl[kk][q] = *(uint32_t*)&l2;
            }
        }

        // ---- O += Ph Vh + Ph Vl + Pl Vh ----
#pragma unroll
        for (int kk = 0; kk < 2; kk++) {
#pragma unroll
            for (int g = 0; g < 8; g++) {
                uint32_t Vh4[4], Vl4[4];
                ldsm4t(Vh4, aVH + kk * (16 * PQ * 2) + g * 32);
                ldsm4t(Vl4, aVL + kk * (16 * PQ * 2) + g * 32);
                mma16816(O[2 * g],     Ph[kk], Vh4[0], Vh4[1]);
                mma16816(O[2 * g + 1], Ph[kk], Vh4[2], Vh4[3]);
                mma16816(O[2 * g],     Ph[kk], Vl4[0], Vl4[1]);
                mma16816(O[2 * g + 1], Ph[kk], Vl4[2], Vl4[3]);
                mma16816(O[2 * g],     Pl[kk], Vh4[0], Vh4[1]);
                mma16816(O[2 * g + 1], Pl[kk], Vh4[2], Vh4[3]);
            }
        }
        __syncthreads();
    }

    // ---- y = O / l, pre-split bf16 hi/lo ----
    {
        const float inv0 = 1.0f / l0, inv1 = 1.0f / l1;
        const int r0 = qb + warp * 16 + (lane >> 2);
        const size_t base0 = ((size_t)b * NSP + r0) * CI + (lane & 3) * 2;
        const size_t base1 = base0 + 8 * CI;
#pragma unroll
        for (int t = 0; t < 16; t++) {
            const float v0 = O[t][0] * inv0, v1 = O[t][1] * inv0;
            __nv_bfloat162 h = __floats2bfloat162_rn(v0, v1);
            *(__nv_bfloat162*)(g_Yh + base0 + t * 8) = h;
            *(__nv_bfloat162*)(g_Yl + base0 + t * 8) = __floats2bfloat162_rn(
                v0 - __bfloat162float(h.x), v1 - __bfloat162float(h.y));
            const float w0 = O[t][2] * inv1, w1 = O[t][3] * inv1;
            __nv_bfloat162 h2 = __floats2bfloat162_rn(w0, w1);
            *(__nv_bfloat162*)(g_Yh + base1 + t * 8) = h2;
            *(__nv_bfloat162*)(g_Yl + base1 + t * 8) = __floats2bfloat162_rn(
                w0 - __bfloat162float(h2.x), w1 - __bfloat162float(h2.y));
        }
    }
}

// ============================================================
// Kernel 4: out = W*y + b + x, co=128 x n=64 tiles, 2 CTAs/SM, cp.async.
// grid (98, 2, 8), 256 threads.
// ============================================================
#define OW_WL 34816
#define OW_YH 69632
#define OW_YL 87040
#define OUT_SMEM 104448

__global__ __launch_bounds__(256) void out_kernel(
    const float* __restrict__ x, const float* __restrict__ Wb,
    float* __restrict__ out)
{
    extern __shared__ __align__(16) char ps[];
    const int tid = threadIdx.x, lane = tid & 31, warp = tid >> 5;
    const int nb = blockIdx.x * 64, co0 = blockIdx.y * 128, b = blockIdx.z;
    const uint32_t sb = smem_u32(ps);

    // cp.async W (pre-split) and Y tiles
    for (int i = tid; i < 2048; i += 256) {
        const int co = i >> 4, s = i & 15;
        const size_t gsrc = (size_t)(co0 + co) * CI + s * 8;
        CP_ASYNC16(sb + co * 272 + s * 16,         g_OWh + gsrc);
        CP_ASYNC16(sb + OW_WL + co * 272 + s * 16, g_OWl + gsrc);
    }
    {
        const __nv_bfloat16* yh = g_Yh + ((size_t)b * NSP + nb) * CI;
        const __nv_bfloat16* yl = g_Yl + ((size_t)b * NSP + nb) * CI;
        for (int i = tid; i < 1024; i += 256) {
            const int n = i >> 4, s = i & 15;
            const size_t gsrc = (size_t)n * CI + s * 8;
            CP_ASYNC16(sb + OW_YH + n * 272 + s * 16, yh + gsrc);
            CP_ASYNC16(sb + OW_YL + n * 272 + s * 16, yl + gsrc);
        }
    }
    CP_COMMIT();
    CP_WAIT0();
    __syncthreads();

    float D[8][4];
#pragma unroll
    for (int t = 0; t < 8; t++)
#pragma unroll
        for (int j = 0; j < 4; j++) D[t][j] = 0.f;

    const uint32_t aW = sb + ((warp * 16 + (lane & 15)) * 136 + ((lane >> 4) << 3)) * 2;
    const uint32_t kRow = (lane & 7) + ((lane >> 4) << 3);
    const uint32_t aY = sb + OW_YH + (kRow * 136 + (((lane >> 3) & 1) << 3)) * 2;

#pragma unroll
    for (int kk = 0; kk < 8; kk++) {
        uint32_t Ah[4], Al[4];
        ldsm4(Ah, aW + kk * 32);
        ldsm4(Al, aW + OW_WL + kk * 32);
#pragma unroll
        for (int g = 0; g < 4; g++) {
            uint32_t Bh[4], Bl[4];
            ldsm4(Bh, aY + g * (16 * 136 * 2) + kk * 32);
            ldsm4(Bl, aY + (OW_YL - OW_YH) + g * (16 * 136 * 2) + kk * 32);
            mma16816(D[2 * g],     Ah, Bh[0], Bh[1]);
            mma16816(D[2 * g + 1], Ah, Bh[2], Bh[3]);
            mma16816(D[2 * g],     Ah, Bl[0], Bl[1]);
            mma16816(D[2 * g + 1], Ah, Bl[2], Bl[3]);
            mma16816(D[2 * g],     Al, Bh[0], Bh[1]);
            mma16816(D[2 * g + 1], Al, Bh[2], Bh[3]);
        }
    }

    const int co = co0 + warp * 16 + (lane >> 2);
    const float bias0 = Wb[co], bias1 = Wb[co + 8];
    const float* xr0 = x + ((size_t)b * CIN + co) * NSP + nb;
    const float* xr1 = xr0 + (size_t)8 * NSP;
    float* o0 = out + ((size_t)b * CIN + co) * NSP + nb;
    float* o1 = o0 + (size_t)8 * NSP;
#pragma unroll
    for (int t = 0; t < 8; t++) {
        const int n = t * 8 + (lane & 3) * 2;
        const float2 xv0 = *(const float2*)(xr0 + n);
        *(float2*)(o0 + n) = make_float2(D[t][0] + bias0 + xv0.x,
                                         D[t][1] + bias0 + xv0.y);
        const float2 xv1 = *(const float2*)(xr1 + n);
        *(float2*)(o1 + n) = make_float2(D[t][2] + bias1 + xv1.x,
                                         D[t][3] + bias1 + xv1.y);
    }
}

// ============================================================
extern "C" void kernel_launch(void* const* d_in, const int* in_sizes, int n_in,
                              void* d_out, int out_size)
{
    const float* x    = (const float*)d_in[0];
    const float* g_w  = (const float*)d_in[1];
    const float* g_b  = (const float*)d_in[2];
    const float* th_w = (const float*)d_in[3];
    const float* th_b = (const float*)d_in[4];
    const float* ph_w = (const float*)d_in[5];
    const float* ph_b = (const float*)d_in[6];
    const float* W_w  = (const float*)d_in[7];
    const float* W_b  = (const float*)d_in[8];
    float* out = (float*)d_out;

    cudaFuncSetAttribute(proj_kernel,
                         cudaFuncAttributeMaxDynamicSharedMemorySize, PROJ_SMEM);
    cudaFuncSetAttribute(attn_kernel,
                         cudaFuncAttributeMaxDynamicSharedMemorySize, ATTN_SMEM);
    cudaFuncSetAttribute(out_kernel,
                         cudaFuncAttributeMaxDynamicSharedMemorySize, OUT_SMEM);

    prep_kernel<<<512, 256>>>(th_w, ph_w, g_w, W_w);

    dim3 g1(NSP / 128, BATCH);
    proj_kernel<<<g1, 256, PROJ_SMEM>>>(x, th_b, ph_b, g_b);

    pool_kernel<<<BATCH * MSP, 128>>>();

    dim3 g2(NSP / 64, BATCH);
    attn_kernel<<<g2, 128, ATTN_SMEM>>>();

    dim3 g3(NSP / 64, CIN / 128, BATCH);
    out_kernel<<<g3, 256, OUT_SMEM>>>(x, W_b, out);
}